// round 1
// baseline (speedup 1.0000x reference)
#include <cuda_runtime.h>
#include <math.h>
#include <stdint.h>

// ---------------------------------------------------------------------------
// Problem constants
// ---------------------------------------------------------------------------
#define NCELL 8192
#define NINP  2000
#define HDIM  128
#define NOUTD 32
#define BN_EPS 1e-3f

// GEMM tiling
#define BM 128
#define BN 128
#define BK 16

// ---------------------------------------------------------------------------
// Scratch (static device buffers; no allocation allowed)
// ---------------------------------------------------------------------------
__device__ float g_bufA[NCELL * HDIM];      // 4 MB
__device__ float g_bufB[NCELL * HDIM];      // 4 MB
__device__ float g_qkv [NCELL * 3 * HDIM];  // 12 MB
__device__ float g_kagg[NCELL * HDIM];      // 4 MB
__device__ float g_stats[512];              // sum[128], sumsq[128], scale[128], shift[128]

// ---------------------------------------------------------------------------
// Packed fp32x2 FMA (Blackwell): 2x FFMA throughput vs scalar FFMA (rt 1 vs 2)
// ---------------------------------------------------------------------------
__device__ __forceinline__ void fma2(float2 &c, const float2 &a, const float2 &b) {
    unsigned long long       &cc = reinterpret_cast<unsigned long long &>(c);
    const unsigned long long &aa = reinterpret_cast<const unsigned long long &>(a);
    const unsigned long long &bb = reinterpret_cast<const unsigned long long &>(b);
    asm("fma.rn.f32x2 %0, %1, %2, %0;" : "+l"(cc) : "l"(aa), "l"(bb));
}

// ---------------------------------------------------------------------------
// Tiled SGEMM:  C[M,N] (+)= alpha * A @ op(B) (+ bias)
//   NT=false: B is [K,N] row-major  (C = A @ B)
//   NT=true : B is [N,K] row-major  (C = A @ B^T)
//   ATOMIC=true: atomicAdd epilogue (split-K over gridDim.z; caller memsets C)
//   bias added only by blockIdx.z == 0 partial.
//   hid/headStride: optional device-side head offset applied to B.
// Requirements: M % 128 == 0, N % 128 == 0 per grid.y tiles, K % 16 == 0.
// ---------------------------------------------------------------------------
template <bool NT, bool ATOMIC>
__global__ void __launch_bounds__(256)
gemm_tile(const float *__restrict__ A, const float *__restrict__ Bbase,
          float *__restrict__ C,
          int lda, int ldb, int ldc, int K,
          float alpha, const float *__restrict__ bias,
          const int *__restrict__ hid, long long headStride)
{
    const float *B = Bbase + (hid ? (long long)hid[0] * headStride : 0);

    __shared__ float As[BK][BM + 4];
    __shared__ float Bs[BK][BN + 4];

    const int tid = threadIdx.x;
    const int tx = tid & 15;
    const int ty = tid >> 4;
    const int m0 = blockIdx.x * BM;
    const int n0 = blockIdx.y * BN;

    // split-K chunk range
    const int chunks = K / BK;
    const int nz = gridDim.z, z = blockIdx.z;
    const int per = chunks / nz, rem = chunks % nz;
    const int c0 = z * per + (z < rem ? z : rem);
    const int c1 = c0 + per + (z < rem ? 1 : 0);

    // loader index mapping (each thread loads two float4 per operand per chunk)
    const int f0 = tid, f1 = tid + 256;
    const int aRow0 = f0 >> 2, aK0 = (f0 & 3) * 4;
    const int aRow1 = f1 >> 2, aK1 = (f1 & 3) * 4;
    const int bK0 = f0 >> 5, bN0 = (f0 & 31) * 4;
    const int bK1 = f1 >> 5, bN1 = (f1 & 31) * 4;

    const float *Ap0 = A + (size_t)(m0 + aRow0) * lda + (size_t)c0 * BK + aK0;
    const float *Ap1 = A + (size_t)(m0 + aRow1) * lda + (size_t)c0 * BK + aK1;
    const float *Bp0, *Bp1;
    if (NT) {
        Bp0 = B + (size_t)(n0 + aRow0) * ldb + (size_t)c0 * BK + aK0;
        Bp1 = B + (size_t)(n0 + aRow1) * ldb + (size_t)c0 * BK + aK1;
    } else {
        Bp0 = B + (size_t)(c0 * BK + bK0) * ldb + n0 + bN0;
        Bp1 = B + (size_t)(c0 * BK + bK1) * ldb + n0 + bN1;
    }

    float2 acc[8][4];
#pragma unroll
    for (int i = 0; i < 8; ++i)
#pragma unroll
        for (int j = 0; j < 4; ++j) acc[i][j] = make_float2(0.f, 0.f);

    float4 ra0 = *(const float4 *)Ap0;
    float4 ra1 = *(const float4 *)Ap1;
    float4 rb0 = *(const float4 *)Bp0;
    float4 rb1 = *(const float4 *)Bp1;

    for (int c = c0; c < c1; ++c) {
        __syncthreads();
        // stage current chunk into smem (A transposed to [k][m])
        As[aK0 + 0][aRow0] = ra0.x; As[aK0 + 1][aRow0] = ra0.y;
        As[aK0 + 2][aRow0] = ra0.z; As[aK0 + 3][aRow0] = ra0.w;
        As[aK1 + 0][aRow1] = ra1.x; As[aK1 + 1][aRow1] = ra1.y;
        As[aK1 + 2][aRow1] = ra1.z; As[aK1 + 3][aRow1] = ra1.w;
        if (NT) {
            Bs[aK0 + 0][aRow0] = rb0.x; Bs[aK0 + 1][aRow0] = rb0.y;
            Bs[aK0 + 2][aRow0] = rb0.z; Bs[aK0 + 3][aRow0] = rb0.w;
            Bs[aK1 + 0][aRow1] = rb1.x; Bs[aK1 + 1][aRow1] = rb1.y;
            Bs[aK1 + 2][aRow1] = rb1.z; Bs[aK1 + 3][aRow1] = rb1.w;
        } else {
            *(float4 *)&Bs[bK0][bN0] = rb0;
            *(float4 *)&Bs[bK1][bN1] = rb1;
        }
        __syncthreads();

        // prefetch next chunk into registers
        if (c + 1 < c1) {
            Ap0 += BK; Ap1 += BK;
            ra0 = *(const float4 *)Ap0;
            ra1 = *(const float4 *)Ap1;
            if (NT) {
                Bp0 += BK; Bp1 += BK;
            } else {
                Bp0 += (size_t)BK * ldb; Bp1 += (size_t)BK * ldb;
            }
            rb0 = *(const float4 *)Bp0;
            rb1 = *(const float4 *)Bp1;
        }

        // microkernel: 8x8 per thread using packed fp32x2 FMA
#pragma unroll
        for (int kk = 0; kk < BK; ++kk) {
            float4 a0 = *(const float4 *)&As[kk][ty * 4];
            float4 a1 = *(const float4 *)&As[kk][64 + ty * 4];
            float4 b0 = *(const float4 *)&Bs[kk][tx * 4];
            float4 b1 = *(const float4 *)&Bs[kk][64 + tx * 4];
            float av[8] = {a0.x, a0.y, a0.z, a0.w, a1.x, a1.y, a1.z, a1.w};
            float2 bp[4] = {make_float2(b0.x, b0.y), make_float2(b0.z, b0.w),
                            make_float2(b1.x, b1.y), make_float2(b1.z, b1.w)};
#pragma unroll
            for (int i = 0; i < 8; ++i) {
                float2 aa = make_float2(av[i], av[i]);
#pragma unroll
                for (int j = 0; j < 4; ++j) fma2(acc[i][j], aa, bp[j]);
            }
        }
    }

    // epilogue
    float bad0[4] = {0.f, 0.f, 0.f, 0.f}, bad1[4] = {0.f, 0.f, 0.f, 0.f};
    if (bias != nullptr && blockIdx.z == 0) {
#pragma unroll
        for (int j = 0; j < 4; ++j) {
            bad0[j] = bias[n0 + tx * 4 + j];
            bad1[j] = bias[n0 + 64 + tx * 4 + j];
        }
    }
#pragma unroll
    for (int i = 0; i < 8; ++i) {
        int r = m0 + ((i < 4) ? (ty * 4 + i) : (64 + ty * 4 + (i - 4)));
        float v[8] = {acc[i][0].x, acc[i][0].y, acc[i][1].x, acc[i][1].y,
                      acc[i][2].x, acc[i][2].y, acc[i][3].x, acc[i][3].y};
        float *crow = C + (size_t)r * ldc;
        if (ATOMIC) {
#pragma unroll
            for (int j = 0; j < 4; ++j)
                atomicAdd(crow + n0 + tx * 4 + j, v[j] * alpha + bad0[j]);
#pragma unroll
            for (int j = 0; j < 4; ++j)
                atomicAdd(crow + n0 + 64 + tx * 4 + j, v[4 + j] * alpha + bad1[j]);
        } else {
            float4 w0 = make_float4(v[0] * alpha + bad0[0], v[1] * alpha + bad0[1],
                                    v[2] * alpha + bad0[2], v[3] * alpha + bad0[3]);
            float4 w1 = make_float4(v[4] * alpha + bad1[0], v[5] * alpha + bad1[1],
                                    v[6] * alpha + bad1[2], v[7] * alpha + bad1[3]);
            *(float4 *)(crow + n0 + tx * 4) = w0;
            *(float4 *)(crow + n0 + 64 + tx * 4) = w1;
        }
    }
}

// ---------------------------------------------------------------------------
// BatchNorm (training-mode, biased var) + ReLU, three small kernels
// ---------------------------------------------------------------------------
__global__ void bn_stats(const float *__restrict__ h, float *__restrict__ stats)
{
    int col = threadIdx.x;          // 128 threads = 128 columns
    int r0 = blockIdx.x * 128;      // 64 blocks * 128 rows
    float s = 0.f, s2 = 0.f;
    for (int r = 0; r < 128; ++r) {
        float v = h[(size_t)(r0 + r) * HDIM + col];
        s += v; s2 += v * v;
    }
    atomicAdd(&stats[col], s);
    atomicAdd(&stats[128 + col], s2);
}

__global__ void bn_finalize(float *__restrict__ stats,
                            const float *__restrict__ g, const float *__restrict__ be,
                            const int *__restrict__ hid, int headStride)
{
    int c = threadIdx.x;
    int off = hid ? hid[0] * headStride : 0;
    float mean = stats[c] * (1.f / (float)NCELL);
    float var = stats[128 + c] * (1.f / (float)NCELL) - mean * mean;
    float rstd = rsqrtf(var + BN_EPS);
    float gg = g[off + c];
    stats[256 + c] = gg * rstd;                  // scale
    stats[384 + c] = be[off + c] - gg * mean * rstd; // shift
}

__global__ void bn_apply(float *__restrict__ h, const float *__restrict__ stats)
{
    const float *scale = stats + 256;
    const float *shift = stats + 384;
    int i = blockIdx.x * blockDim.x + threadIdx.x; // one float4 each, 262144 threads
    float4 v = ((float4 *)h)[i];
    int c = (i * 4) & (HDIM - 1);
    v.x = fmaxf(v.x * scale[c + 0] + shift[c + 0], 0.f);
    v.y = fmaxf(v.y * scale[c + 1] + shift[c + 1], 0.f);
    v.z = fmaxf(v.z * scale[c + 2] + shift[c + 2], 0.f);
    v.w = fmaxf(v.w * scale[c + 3] + shift[c + 3], 0.f);
    ((float4 *)h)[i] = v;
}

// ---------------------------------------------------------------------------
// In-place row softmax over [8192, 8192], one block per row, row in smem
// ---------------------------------------------------------------------------
__global__ void softmax_row(float *__restrict__ attn)
{
    extern __shared__ float row[];   // 8192 floats
    __shared__ float red[256];
    const int t = threadIdx.x;
    float *p = attn + (size_t)blockIdx.x * NCELL;

    float m = -1e30f;
    for (int i = t; i < NCELL / 4; i += 256) {
        float4 v = ((const float4 *)p)[i];
        ((float4 *)row)[i] = v;
        m = fmaxf(m, fmaxf(fmaxf(v.x, v.y), fmaxf(v.z, v.w)));
    }
    red[t] = m; __syncthreads();
    for (int s = 128; s > 0; s >>= 1) {
        if (t < s) red[t] = fmaxf(red[t], red[t + s]);
        __syncthreads();
    }
    const float bmax = red[0];
    __syncthreads();

    float sum = 0.f;
    for (int i = t; i < NCELL / 4; i += 256) {
        float4 v = ((float4 *)row)[i];
        v.x = __expf(v.x - bmax); v.y = __expf(v.y - bmax);
        v.z = __expf(v.z - bmax); v.w = __expf(v.w - bmax);
        sum += v.x + v.y + v.z + v.w;
        ((float4 *)row)[i] = v;
    }
    red[t] = sum; __syncthreads();
    for (int s = 128; s > 0; s >>= 1) {
        if (t < s) red[t] += red[t + s];
        __syncthreads();
    }
    const float inv = 1.f / red[0];
    __syncthreads();

    for (int i = t; i < NCELL / 4; i += 256) {
        float4 v = ((float4 *)row)[i];
        v.x *= inv; v.y *= inv; v.z *= inv; v.w *= inv;
        ((float4 *)p)[i] = v;
    }
}

// ---------------------------------------------------------------------------
// Variational heads: q_m = o@Wm+bm ; q_v = exp(o@Wv+bv) ; latent = q_m + sqrt(q_v)*eps
// 64 blocks x 128 rows; dynamic smem: Wm[128*32] Wv[128*32] osm[128*129]
// ---------------------------------------------------------------------------
__global__ void heads_kernel(const float *__restrict__ o,
                             const float *__restrict__ mW, const float *__restrict__ mb,
                             const float *__restrict__ vW, const float *__restrict__ vb,
                             const float *__restrict__ eps,
                             float *__restrict__ qm, float *__restrict__ qv,
                             float *__restrict__ lat)
{
    extern __shared__ float sm[];
    float *Wm  = sm;                  // 4096
    float *Wv  = sm + 4096;           // 4096
    float *osm = sm + 8192;           // 128*129
    const int t = threadIdx.x;
    const int r0 = blockIdx.x * 128;

    for (int i = t; i < HDIM * NOUTD; i += 256) { Wm[i] = mW[i]; Wv[i] = vW[i]; }
    for (int i = t; i < 128 * HDIM; i += 256) {
        int r = i >> 7, c = i & 127;
        osm[r * 129 + c] = o[(size_t)(r0 + r) * HDIM + c];
    }
    __syncthreads();

    for (int idx = t; idx < 128 * NOUTD; idx += 256) {
        int r = idx >> 5, c = idx & 31;
        const float *orow = &osm[r * 129];
        float dm = 0.f, dv = 0.f;
#pragma unroll 8
        for (int k = 0; k < HDIM; ++k) {
            float ov = orow[k];
            dm += ov * Wm[k * NOUTD + c];
            dv += ov * Wv[k * NOUTD + c];
        }
        int R = r0 + r;
        float mval = dm + mb[c];
        float vval = __expf(dv + vb[c]);
        qm[R * NOUTD + c]  = mval;
        qv[R * NOUTD + c]  = vval;
        lat[R * NOUTD + c] = mval + sqrtf(vval) * eps[R * NOUTD + c];
    }
}

// ---------------------------------------------------------------------------
// Launch
// ---------------------------------------------------------------------------
extern "C" void kernel_launch(void *const *d_in, const int *in_sizes, int n_in,
                              void *d_out, int out_size)
{
    const float *x       = (const float *)d_in[0];
    const float *spatial = (const float *)d_in[1];
    const float *eps     = (const float *)d_in[2];
    const float *enc_W   = (const float *)d_in[3];
    // d_in[4] enc_b : cancels under BatchNorm
    const float *enc_g   = (const float *)d_in[5];
    const float *enc_be  = (const float *)d_in[6];
    const float *sh_W1   = (const float *)d_in[7];
    // d_in[8] sh_b1 : cancels
    const float *sh_g1   = (const float *)d_in[9];
    const float *sh_be1  = (const float *)d_in[10];
    const float *sh_W2   = (const float *)d_in[11];
    // d_in[12] sh_b2 : cancels
    const float *sh_g2   = (const float *)d_in[13];
    const float *sh_be2  = (const float *)d_in[14];
    const float *qkv_W   = (const float *)d_in[15];
    const float *qkv_b   = (const float *)d_in[16];
    const float *o_W     = (const float *)d_in[17];
    const float *o_b     = (const float *)d_in[18];
    const float *mean_W  = (const float *)d_in[19];
    const float *mean_b  = (const float *)d_in[20];
    const float *var_W   = (const float *)d_in[21];
    const float *var_b   = (const float *)d_in[22];
    const int   *hid     = (const int *)d_in[23];

    float *out = (float *)d_out;
    float *out_qm   = out;
    float *out_qv   = out + (size_t)NCELL * NOUTD;
    float *out_lat  = out + 2 * (size_t)NCELL * NOUTD;
    float *out_attn = out + 3 * (size_t)NCELL * NOUTD;

    float *bufA, *bufB, *qkv, *kagg, *stats;
    cudaGetSymbolAddress((void **)&bufA, g_bufA);
    cudaGetSymbolAddress((void **)&bufB, g_bufB);
    cudaGetSymbolAddress((void **)&qkv,  g_qkv);
    cudaGetSymbolAddress((void **)&kagg, g_kagg);
    cudaGetSymbolAddress((void **)&stats, g_stats);

    const size_t NH_BYTES = (size_t)NCELL * HDIM * sizeof(float);
    const float SCALE = 0.08838834764831845f; // 1/sqrt(128)

    // 1. head-specific encoder: h_pre = x @ enc_W[hid]     (bias cancels in BN)
    cudaMemsetAsync(bufA, 0, NH_BYTES);
    gemm_tile<false, true><<<dim3(64, 1, 4), 256>>>(
        x, enc_W, bufA, NINP, HDIM, HDIM, NINP, 1.f, nullptr, hid,
        (long long)NINP * HDIM);
    cudaMemsetAsync(stats, 0, 256 * sizeof(float));
    bn_stats<<<64, 128>>>(bufA, stats);
    bn_finalize<<<1, 128>>>(stats, enc_g, enc_be, hid, HDIM);
    bn_apply<<<1024, 256>>>(bufA, stats);

    // 2. shared layer 1
    cudaMemsetAsync(bufB, 0, NH_BYTES);
    gemm_tile<false, true><<<dim3(64, 1, 2), 256>>>(
        bufA, sh_W1, bufB, HDIM, HDIM, HDIM, HDIM, 1.f, nullptr, nullptr, 0);
    cudaMemsetAsync(stats, 0, 256 * sizeof(float));
    bn_stats<<<64, 128>>>(bufB, stats);
    bn_finalize<<<1, 128>>>(stats, sh_g1, sh_be1, nullptr, 0);
    bn_apply<<<1024, 256>>>(bufB, stats);

    // 3. shared layer 2
    cudaMemsetAsync(bufA, 0, NH_BYTES);
    gemm_tile<false, true><<<dim3(64, 1, 2), 256>>>(
        bufB, sh_W2, bufA, HDIM, HDIM, HDIM, HDIM, 1.f, nullptr, nullptr, 0);
    cudaMemsetAsync(stats, 0, 256 * sizeof(float));
    bn_stats<<<64, 128>>>(bufA, stats);
    bn_finalize<<<1, 128>>>(stats, sh_g2, sh_be2, nullptr, 0);
    bn_apply<<<1024, 256>>>(bufA, stats);

    // 4. qkv projection: [N, 384]
    cudaMemsetAsync(qkv, 0, (size_t)NCELL * 3 * HDIM * sizeof(float));
    gemm_tile<false, true><<<dim3(64, 3, 2), 256>>>(
        bufA, qkv_W, qkv, HDIM, 3 * HDIM, 3 * HDIM, HDIM, 1.f, qkv_b, nullptr, 0);

    // 5. k_agg = spatial @ k
    cudaMemsetAsync(kagg, 0, NH_BYTES);
    gemm_tile<false, true><<<dim3(64, 1, 4), 256>>>(
        spatial, qkv + HDIM, kagg, NCELL, 3 * HDIM, HDIM, NCELL, 1.f, nullptr,
        nullptr, 0);

    // 6. logits = (q @ k_agg^T) / sqrt(H)  -> written straight into attn output
    gemm_tile<true, false><<<dim3(64, 64, 1), 256>>>(
        qkv, kagg, out_attn, 3 * HDIM, HDIM, NCELL, HDIM, SCALE, nullptr,
        nullptr, 0);

    // 7. softmax in place
    softmax_row<<<NCELL, 256, NCELL * sizeof(float)>>>(out_attn);

    // 8. av = attn @ v
    cudaMemsetAsync(bufA, 0, NH_BYTES);
    gemm_tile<false, true><<<dim3(64, 1, 4), 256>>>(
        out_attn, qkv + 2 * HDIM, bufA, NCELL, 3 * HDIM, HDIM, NCELL, 1.f,
        nullptr, nullptr, 0);

    // 9. o = av @ o_W + o_b
    cudaMemsetAsync(bufB, 0, NH_BYTES);
    gemm_tile<false, true><<<dim3(64, 1, 2), 256>>>(
        bufA, o_W, bufB, HDIM, HDIM, HDIM, HDIM, 1.f, o_b, nullptr, 0);

    // 10. variational heads
    const int heads_smem = (4096 + 4096 + 128 * 129) * sizeof(float);
    cudaFuncSetAttribute(heads_kernel, cudaFuncAttributeMaxDynamicSharedMemorySize,
                         heads_smem);
    heads_kernel<<<64, 256, heads_smem>>>(bufB, mean_W, mean_b, var_W, var_b,
                                          eps, out_qm, out_qv, out_lat);
}

// round 3
// speedup vs baseline: 1.0319x; 1.0319x over previous
#include <cuda_runtime.h>
#include <cuda_bf16.h>
#include <math.h>
#include <stdint.h>

// ---------------------------------------------------------------------------
// Problem constants
// ---------------------------------------------------------------------------
#define NCELL 8192
#define NINP  2000
#define HDIM  128
#define NOUTD 32
#define BN_EPS 1e-3f

// fp32 GEMM tiling
#define BM 128
#define BN 128
#define BK 16

// Arch-specific gate: tcgen05 only exists on the sm_103a (arch-specific)
// compilation target. The harness also builds a plain sm_103 target; this
// macro keeps tcgen05 PTX out of that target entirely.
#if defined(__CUDA_ARCH_FEAT_SM103_ALL) || defined(__CUDA_ARCH_FEAT_SM100_ALL) || \
    defined(__CUDA_ARCH_FEAT_SM110_ALL) || defined(__CUDA_ARCH_FEAT_SM101_ALL)
#define TC_ENABLED 1
#else
#define TC_ENABLED 0
#endif

// ---------------------------------------------------------------------------
// Scratch (static device buffers; no runtime allocation allowed)
// ---------------------------------------------------------------------------
__device__ __align__(256) float g_bufA[NCELL * HDIM];
__device__ __align__(256) float g_bufB[NCELL * HDIM];
__device__ __align__(256) float g_qkv [NCELL * 3 * HDIM];
__device__ __align__(256) float g_kagg[NCELL * HDIM];
__device__ __align__(256) float g_stats[512];

// bf16 hi/lo split operands for tensor-core GEMMs
__device__ __align__(256) __nv_bfloat16 g_sp_hi[(size_t)NCELL * NCELL];
__device__ __align__(256) __nv_bfloat16 g_sp_lo[(size_t)NCELL * NCELL];
__device__ __align__(256) __nv_bfloat16 g_at_hi[(size_t)NCELL * NCELL];
__device__ __align__(256) __nv_bfloat16 g_at_lo[(size_t)NCELL * NCELL];
__device__ __align__(256) __nv_bfloat16 g_q_hi [NCELL * HDIM];
__device__ __align__(256) __nv_bfloat16 g_q_lo [NCELL * HDIM];
__device__ __align__(256) __nv_bfloat16 g_ka_hi[NCELL * HDIM];
__device__ __align__(256) __nv_bfloat16 g_ka_lo[NCELL * HDIM];
__device__ __align__(256) __nv_bfloat16 g_kT_hi[HDIM * NCELL];
__device__ __align__(256) __nv_bfloat16 g_kT_lo[HDIM * NCELL];
__device__ __align__(256) __nv_bfloat16 g_vT_hi[HDIM * NCELL];
__device__ __align__(256) __nv_bfloat16 g_vT_lo[HDIM * NCELL];

// ---------------------------------------------------------------------------
// Inline PTX helpers (generic targets: mbarrier/elect are sm_90+ safe)
// ---------------------------------------------------------------------------
__device__ __forceinline__ uint32_t cvta_smem(const void *p) {
    uint32_t a;
    asm("{ .reg .u64 t; cvta.to.shared.u64 t, %1; cvt.u32.u64 %0, t; }"
        : "=r"(a) : "l"(p));
    return a;
}
__device__ __forceinline__ uint32_t elect_one() {
    uint32_t p;
    asm volatile("{ .reg .pred p; elect.sync _|p, 0xFFFFFFFF; selp.b32 %0, 1, 0, p; }"
                 : "=r"(p));
    return p;
}
__device__ __forceinline__ void mbar_init(uint32_t mbar, uint32_t cnt) {
    asm volatile("mbarrier.init.shared.b64 [%0], %1;"
                 :: "r"(mbar), "r"(cnt) : "memory");
}
__device__ __forceinline__ void mbar_wait(uint32_t mbar, uint32_t parity) {
    asm volatile(
        "{\n\t.reg .pred P;\n"
        "LW_%=:\n\t"
        "mbarrier.try_wait.parity.acquire.cta.shared::cta.b64 P, [%0], %1, 0x989680;\n\t"
        "@P bra LD_%=;\n\t"
        "bra LW_%=;\n"
        "LD_%=:\n\t}"
        :: "r"(mbar), "r"(parity) : "memory");
}
__device__ __forceinline__ void fence_async_smem() {
    asm volatile("fence.proxy.async.shared::cta;" ::: "memory");
}

// ---- tcgen05 helpers: only instantiated from inside the TC_ENABLED region ----
__device__ __forceinline__ void tc_alloc(uint32_t smem_dst, uint32_t ncols) {
    asm volatile("tcgen05.alloc.cta_group::1.sync.aligned.shared::cta.b32 [%0], %1;"
                 :: "r"(smem_dst), "r"(ncols) : "memory");
}
__device__ __forceinline__ void tc_dealloc(uint32_t tmem, uint32_t ncols) {
    asm volatile("tcgen05.dealloc.cta_group::1.sync.aligned.b32 %0, %1;"
                 :: "r"(tmem), "r"(ncols));
}
__device__ __forceinline__ void tc_relinquish() {
    asm volatile("tcgen05.relinquish_alloc_permit.cta_group::1.sync.aligned;");
}
__device__ __forceinline__ void tc_commit(uint32_t mbar) {
    asm volatile("tcgen05.commit.cta_group::1.mbarrier::arrive::one.shared::cluster.b64 [%0];"
                 :: "r"(mbar) : "memory");
}
__device__ __forceinline__ void tc_fence_after() {
    asm volatile("tcgen05.fence::after_thread_sync;" ::: "memory");
}
__device__ __forceinline__ void tc_wait_ld() {
    asm volatile("tcgen05.wait::ld.sync.aligned;" ::: "memory");
}
__device__ __forceinline__ void ldtm32(uint32_t *r, uint32_t addr) {
    asm volatile(
        "tcgen05.ld.sync.aligned.32x32b.x32.b32 "
        "{%0, %1, %2, %3, %4, %5, %6, %7, "
        " %8, %9, %10, %11, %12, %13, %14, %15, "
        " %16, %17, %18, %19, %20, %21, %22, %23, "
        " %24, %25, %26, %27, %28, %29, %30, %31}, [%32];"
        : "=r"(r[0]),  "=r"(r[1]),  "=r"(r[2]),  "=r"(r[3]),
          "=r"(r[4]),  "=r"(r[5]),  "=r"(r[6]),  "=r"(r[7]),
          "=r"(r[8]),  "=r"(r[9]),  "=r"(r[10]), "=r"(r[11]),
          "=r"(r[12]), "=r"(r[13]), "=r"(r[14]), "=r"(r[15]),
          "=r"(r[16]), "=r"(r[17]), "=r"(r[18]), "=r"(r[19]),
          "=r"(r[20]), "=r"(r[21]), "=r"(r[22]), "=r"(r[23]),
          "=r"(r[24]), "=r"(r[25]), "=r"(r[26]), "=r"(r[27]),
          "=r"(r[28]), "=r"(r[29]), "=r"(r[30]), "=r"(r[31])
        : "r"(addr));
}
// SS bf16 MMA, cta_group::1, fp32 accumulate
__device__ __forceinline__ void mma_f16_ss(uint32_t d, uint64_t a_desc,
                                           uint64_t b_desc, uint32_t idesc,
                                           uint32_t en) {
    asm volatile(
        "{\n\t.reg .pred p;\n\t"
        "setp.ne.u32 p, %5, 0;\n\t"
        "tcgen05.mma.cta_group::1.kind::f16 [%0], %1, %2, %3, {%4, %4, %4, %4}, p;\n\t}"
        :: "r"(d), "l"(a_desc), "l"(b_desc), "r"(idesc), "r"(0u), "r"(en)
        : "memory");
}
// SW128 smem descriptor (K-major, SBO=64, LBO=1, version=1)
__device__ __forceinline__ uint64_t make_desc(uint32_t addr) {
    return ((uint64_t)2 << 61) | ((uint64_t)1 << 46) | ((uint64_t)64 << 32) |
           ((uint64_t)1 << 16) | (((uint64_t)(addr >> 4)) & 0x3FFF);
}
// fp32x2 packed FMA
__device__ __forceinline__ void fma2(float2 &c, const float2 &a, const float2 &b) {
    unsigned long long       &cc = reinterpret_cast<unsigned long long &>(c);
    const unsigned long long &aa = reinterpret_cast<const unsigned long long &>(a);
    const unsigned long long &bb = reinterpret_cast<const unsigned long long &>(b);
    asm("fma.rn.f32x2 %0, %1, %2, %0;" : "+l"(cc) : "l"(aa), "l"(bb));
}
__device__ __forceinline__ void split1(float v, __nv_bfloat16 &h, __nv_bfloat16 &l) {
    h = __float2bfloat16(v);
    l = __float2bfloat16(v - __bfloat162float(h));
}

// ---------------------------------------------------------------------------
// Tensor-core GEMM:  C[128-tile, 128-tile] = alpha * (Ahi+Alo) @ (Bhi+Blo)^T
// A: [M, K] bf16 K-major; B: [Ntot, K] bf16 K-major.
// Blocked-atom SW128 layout (16 atom-rows per atom-col, atom-col stride 16KB),
// K=128 per iteration, split-K over gridDim.z.
// ATOMIC => atomicAdd fp32 epilogue (caller zero-fills C).
// ---------------------------------------------------------------------------
#define SM_AHI 1024
#define SM_ALO (1024 + 32768)
#define SM_BHI (1024 + 65536)
#define SM_BLO (1024 + 98304)
#define SM_TOTAL (1024 + 131072)
static constexpr uint32_t TC_IDESC = 0x8200490u; // F32 accum, BF16xBF16, M=128, N=128

__device__ __forceinline__ uint32_t sw_off(int r, int ch) {
    // 128 rows x 128 bf16 tile; ch = 16B chunk index within row (0..15)
    int atom = (r >> 3) + (ch >> 3) * 16;
    uint32_t byte = atom * 1024 + (r & 7) * 128 + (ch & 7) * 16;
    return byte ^ ((byte >> 3) & 0x70);
}

template <bool ATOMIC>
__global__ void __launch_bounds__(128)
tc_gemm(const __nv_bfloat16 *__restrict__ Ahi, const __nv_bfloat16 *__restrict__ Alo,
        int lda,
        const __nv_bfloat16 *__restrict__ Bhi, const __nv_bfloat16 *__restrict__ Blo,
        int ldb,
        float *__restrict__ C, int ldc, int K, float alpha)
{
#if TC_ENABLED
    extern __shared__ char tc_smem[];
    const uint32_t sb = cvta_smem(tc_smem);
    const int tid = threadIdx.x;
    const int wid = tid >> 5;

    if (wid == 0) tc_alloc(sb + 0, 128);
    if (tid == 64) mbar_init(sb + 8, 1);
    __syncthreads();
    uint32_t tmem;
    asm volatile("ld.shared.b32 %0, [%1];" : "=r"(tmem) : "r"(sb + 0));

    const int m0 = blockIdx.x * 128;
    const int n0 = blockIdx.y * 128;
    const int kTiles = K >> 7;
    const int per = kTiles / gridDim.z;
    const int kt0 = blockIdx.z * per, kt1 = kt0 + per;

    uint32_t phase = 0;
    for (int kt = kt0; kt < kt1; ++kt) {
        const size_t kb = (size_t)kt << 7;
        // stage 4 tiles (A hi/lo, B hi/lo), 128x128 bf16 each, swizzled
        for (int idx = tid; idx < 2048; idx += 128) {
            int r = idx >> 4, ch = idx & 15;
            uint32_t so = sw_off(r, ch);
            size_t aoff = (size_t)(m0 + r) * lda + kb + ch * 8;
            size_t boff = (size_t)(n0 + r) * ldb + kb + ch * 8;
            *(uint4 *)(tc_smem + SM_AHI + so) = *(const uint4 *)(Ahi + aoff);
            *(uint4 *)(tc_smem + SM_ALO + so) = *(const uint4 *)(Alo + aoff);
            *(uint4 *)(tc_smem + SM_BHI + so) = *(const uint4 *)(Bhi + boff);
            *(uint4 *)(tc_smem + SM_BLO + so) = *(const uint4 *)(Blo + boff);
        }
        fence_async_smem();
        __syncthreads();

        if (wid == 0) {
            if (elect_one()) {
                uint64_t da_h = make_desc(sb + SM_AHI);
                uint64_t da_l = make_desc(sb + SM_ALO);
                uint64_t db_h = make_desc(sb + SM_BHI);
                uint64_t db_l = make_desc(sb + SM_BLO);
#pragma unroll
                for (int k = 0; k < 8; ++k) {
                    uint64_t off = (uint64_t)((k & 3) * 2 + (k >> 2) * 1024);
                    uint32_t en0 = (kt > kt0) || (k > 0);
                    mma_f16_ss(tmem, da_h + off, db_h + off, TC_IDESC, en0);
                    mma_f16_ss(tmem, da_h + off, db_l + off, TC_IDESC, 1u);
                    mma_f16_ss(tmem, da_l + off, db_h + off, TC_IDESC, 1u);
                }
                tc_commit(sb + 8);
            }
        }
        mbar_wait(sb + 8, phase);
        phase ^= 1;
        __syncthreads();
    }

    // epilogue: D[row=tid, 0..127] from TMEM
    tc_fence_after();
    const int row = tid;
    for (int part = 0; part < 4; ++part) {
        uint32_t d[32];
        ldtm32(d, tmem + part * 32);
        tc_wait_ld();
        if (ATOMIC) {
            float *cp = C + (size_t)(m0 + row) * ldc + n0 + part * 32;
#pragma unroll
            for (int c = 0; c < 32; ++c)
                atomicAdd(cp + c, __uint_as_float(d[c]) * alpha);
        } else {
            float *st = (float *)tc_smem;  // header/mbar no longer needed
#pragma unroll
            for (int c = 0; c < 32; ++c)
                st[row * 33 + c] = __uint_as_float(d[c]) * alpha;
            __syncthreads();
#pragma unroll
            for (int i = 0; i < 32; ++i) {
                int idx = i * 128 + tid;
                int rr = idx >> 5, cc = idx & 31;
                C[(size_t)(m0 + rr) * ldc + n0 + part * 32 + cc] = st[rr * 33 + cc];
            }
            __syncthreads();
        }
    }
    __syncthreads();
    if (wid == 0) {
        tc_relinquish();
        tc_dealloc(tmem, 128);
    }
#endif  // TC_ENABLED — non-a target compiles an empty body; never executed on GPU
}

// ---------------------------------------------------------------------------
// fp32 -> bf16 hi/lo split kernels
// ---------------------------------------------------------------------------
__global__ void split_cols(const float *__restrict__ src, int ldsrc, int col0,
                           int cols4, __nv_bfloat16 *__restrict__ hi,
                           __nv_bfloat16 *__restrict__ lo)
{
    int idx = blockIdx.x * blockDim.x + threadIdx.x;
    int r = idx / cols4, c = idx - r * cols4;
    float4 v = *(const float4 *)(src + (size_t)r * ldsrc + col0 + c * 4);
    __nv_bfloat16 h0, h1, h2, h3, l0, l1, l2, l3;
    split1(v.x, h0, l0); split1(v.y, h1, l1);
    split1(v.z, h2, l2); split1(v.w, h3, l3);
    __nv_bfloat162 *ph = (__nv_bfloat162 *)(hi + (size_t)idx * 4);
    __nv_bfloat162 *pl = (__nv_bfloat162 *)(lo + (size_t)idx * 4);
    ph[0] = __nv_bfloat162(h0, h1); ph[1] = __nv_bfloat162(h2, h3);
    pl[0] = __nv_bfloat162(l0, l1); pl[1] = __nv_bfloat162(l2, l3);
}

// transpose + split: dst[c, r] = src[r, col0 + c], dst is [128, NCELL]
__global__ void transpose_split(const float *__restrict__ src, int ldsrc, int col0,
                                __nv_bfloat16 *__restrict__ hi,
                                __nv_bfloat16 *__restrict__ lo)
{
    __shared__ float t[32][33];
    int r0 = blockIdx.x * 32, c0 = blockIdx.y * 32;
    int tx = threadIdx.x, ty = threadIdx.y;  // 32 x 8
#pragma unroll
    for (int i = 0; i < 4; ++i) {
        int r = ty + i * 8;
        t[r][tx] = src[(size_t)(r0 + r) * ldsrc + col0 + c0 + tx];
    }
    __syncthreads();
#pragma unroll
    for (int i = 0; i < 4; ++i) {
        int c = ty + i * 8;
        float v = t[tx][c];
        __nv_bfloat16 h, l;
        split1(v, h, l);
        size_t o = (size_t)(c0 + c) * NCELL + r0 + tx;
        hi[o] = h;
        lo[o] = l;
    }
}

// ---------------------------------------------------------------------------
// fp32 tiled SGEMM (kept for the small GEMMs): C = alpha*A@B (+bias), split-K
// ---------------------------------------------------------------------------
template <bool NT, bool ATOMIC>
__global__ void __launch_bounds__(256)
gemm_tile(const float *__restrict__ A, const float *__restrict__ Bbase,
          float *__restrict__ C,
          int lda, int ldb, int ldc, int K,
          float alpha, const float *__restrict__ bias,
          const int *__restrict__ hid, long long headStride)
{
    const float *B = Bbase + (hid ? (long long)hid[0] * headStride : 0);

    __shared__ float As[BK][BM + 4];
    __shared__ float Bs[BK][BN + 4];

    const int tid = threadIdx.x;
    const int tx = tid & 15;
    const int ty = tid >> 4;
    const int m0 = blockIdx.x * BM;
    const int n0 = blockIdx.y * BN;

    const int chunks = K / BK;
    const int nz = gridDim.z, z = blockIdx.z;
    const int per = chunks / nz, rem = chunks % nz;
    const int c0 = z * per + (z < rem ? z : rem);
    const int c1 = c0 + per + (z < rem ? 1 : 0);

    const int f0 = tid, f1 = tid + 256;
    const int aRow0 = f0 >> 2, aK0 = (f0 & 3) * 4;
    const int aRow1 = f1 >> 2, aK1 = (f1 & 3) * 4;
    const int bK0 = f0 >> 5, bN0 = (f0 & 31) * 4;
    const int bK1 = f1 >> 5, bN1 = (f1 & 31) * 4;

    const float *Ap0 = A + (size_t)(m0 + aRow0) * lda + (size_t)c0 * BK + aK0;
    const float *Ap1 = A + (size_t)(m0 + aRow1) * lda + (size_t)c0 * BK + aK1;
    const float *Bp0, *Bp1;
    if (NT) {
        Bp0 = B + (size_t)(n0 + aRow0) * ldb + (size_t)c0 * BK + aK0;
        Bp1 = B + (size_t)(n0 + aRow1) * ldb + (size_t)c0 * BK + aK1;
    } else {
        Bp0 = B + (size_t)(c0 * BK + bK0) * ldb + n0 + bN0;
        Bp1 = B + (size_t)(c0 * BK + bK1) * ldb + n0 + bN1;
    }

    float2 acc[8][4];
#pragma unroll
    for (int i = 0; i < 8; ++i)
#pragma unroll
        for (int j = 0; j < 4; ++j) acc[i][j] = make_float2(0.f, 0.f);

    float4 ra0 = *(const float4 *)Ap0;
    float4 ra1 = *(const float4 *)Ap1;
    float4 rb0 = *(const float4 *)Bp0;
    float4 rb1 = *(const float4 *)Bp1;

    for (int c = c0; c < c1; ++c) {
        __syncthreads();
        As[aK0 + 0][aRow0] = ra0.x; As[aK0 + 1][aRow0] = ra0.y;
        As[aK0 + 2][aRow0] = ra0.z; As[aK0 + 3][aRow0] = ra0.w;
        As[aK1 + 0][aRow1] = ra1.x; As[aK1 + 1][aRow1] = ra1.y;
        As[aK1 + 2][aRow1] = ra1.z; As[aK1 + 3][aRow1] = ra1.w;
        if (NT) {
            Bs[aK0 + 0][aRow0] = rb0.x; Bs[aK0 + 1][aRow0] = rb0.y;
            Bs[aK0 + 2][aRow0] = rb0.z; Bs[aK0 + 3][aRow0] = rb0.w;
            Bs[aK1 + 0][aRow1] = rb1.x; Bs[aK1 + 1][aRow1] = rb1.y;
            Bs[aK1 + 2][aRow1] = rb1.z; Bs[aK1 + 3][aRow1] = rb1.w;
        } else {
            *(float4 *)&Bs[bK0][bN0] = rb0;
            *(float4 *)&Bs[bK1][bN1] = rb1;
        }
        __syncthreads();

        if (c + 1 < c1) {
            Ap0 += BK; Ap1 += BK;
            ra0 = *(const float4 *)Ap0;
            ra1 = *(const float4 *)Ap1;
            if (NT) {
                Bp0 += BK; Bp1 += BK;
            } else {
                Bp0 += (size_t)BK * ldb; Bp1 += (size_t)BK * ldb;
            }
            rb0 = *(const float4 *)Bp0;
            rb1 = *(const float4 *)Bp1;
        }

#pragma unroll
        for (int kk = 0; kk < BK; ++kk) {
            float4 a0 = *(const float4 *)&As[kk][ty * 4];
            float4 a1 = *(const float4 *)&As[kk][64 + ty * 4];
            float4 b0 = *(const float4 *)&Bs[kk][tx * 4];
            float4 b1 = *(const float4 *)&Bs[kk][64 + tx * 4];
            float av[8] = {a0.x, a0.y, a0.z, a0.w, a1.x, a1.y, a1.z, a1.w};
            float2 bp[4] = {make_float2(b0.x, b0.y), make_float2(b0.z, b0.w),
                            make_float2(b1.x, b1.y), make_float2(b1.z, b1.w)};
#pragma unroll
            for (int i = 0; i < 8; ++i) {
                float2 aa = make_float2(av[i], av[i]);
#pragma unroll
                for (int j = 0; j < 4; ++j) fma2(acc[i][j], aa, bp[j]);
            }
        }
    }

    float bad0[4] = {0.f, 0.f, 0.f, 0.f}, bad1[4] = {0.f, 0.f, 0.f, 0.f};
    if (bias != nullptr && blockIdx.z == 0) {
#pragma unroll
        for (int j = 0; j < 4; ++j) {
            bad0[j] = bias[n0 + tx * 4 + j];
            bad1[j] = bias[n0 + 64 + tx * 4 + j];
        }
    }
#pragma unroll
    for (int i = 0; i < 8; ++i) {
        int r = m0 + ((i < 4) ? (ty * 4 + i) : (64 + ty * 4 + (i - 4)));
        float v[8] = {acc[i][0].x, acc[i][0].y, acc[i][1].x, acc[i][1].y,
                      acc[i][2].x, acc[i][2].y, acc[i][3].x, acc[i][3].y};
        float *crow = C + (size_t)r * ldc;
        if (ATOMIC) {
#pragma unroll
            for (int j = 0; j < 4; ++j)
                atomicAdd(crow + n0 + tx * 4 + j, v[j] * alpha + bad0[j]);
#pragma unroll
            for (int j = 0; j < 4; ++j)
                atomicAdd(crow + n0 + 64 + tx * 4 + j, v[4 + j] * alpha + bad1[j]);
        } else {
            float4 w0 = make_float4(v[0] * alpha + bad0[0], v[1] * alpha + bad0[1],
                                    v[2] * alpha + bad0[2], v[3] * alpha + bad0[3]);
            float4 w1 = make_float4(v[4] * alpha + bad1[0], v[5] * alpha + bad1[1],
                                    v[6] * alpha + bad1[2], v[7] * alpha + bad1[3]);
            *(float4 *)(crow + n0 + tx * 4) = w0;
            *(float4 *)(crow + n0 + 64 + tx * 4) = w1;
        }
    }
}

// ---------------------------------------------------------------------------
// BatchNorm (training-mode) + ReLU
// ---------------------------------------------------------------------------
__global__ void bn_stats(const float *__restrict__ h, float *__restrict__ stats)
{
    int col = threadIdx.x;
    int r0 = blockIdx.x * 128;
    float s = 0.f, s2 = 0.f;
    for (int r = 0; r < 128; ++r) {
        float v = h[(size_t)(r0 + r) * HDIM + col];
        s += v; s2 += v * v;
    }
    atomicAdd(&stats[col], s);
    atomicAdd(&stats[128 + col], s2);
}

__global__ void bn_finalize(float *__restrict__ stats,
                            const float *__restrict__ g, const float *__restrict__ be,
                            const int *__restrict__ hid, int headStride)
{
    int c = threadIdx.x;
    int off = hid ? hid[0] * headStride : 0;
    float mean = stats[c] * (1.f / (float)NCELL);
    float var = stats[128 + c] * (1.f / (float)NCELL) - mean * mean;
    float rstd = rsqrtf(var + BN_EPS);
    float gg = g[off + c];
    stats[256 + c] = gg * rstd;
    stats[384 + c] = be[off + c] - gg * mean * rstd;
}

__global__ void bn_apply(float *__restrict__ h, const float *__restrict__ stats)
{
    const float *scale = stats + 256;
    const float *shift = stats + 384;
    int i = blockIdx.x * blockDim.x + threadIdx.x;
    float4 v = ((float4 *)h)[i];
    int c = (i * 4) & (HDIM - 1);
    v.x = fmaxf(v.x * scale[c + 0] + shift[c + 0], 0.f);
    v.y = fmaxf(v.y * scale[c + 1] + shift[c + 1], 0.f);
    v.z = fmaxf(v.z * scale[c + 2] + shift[c + 2], 0.f);
    v.w = fmaxf(v.w * scale[c + 3] + shift[c + 3], 0.f);
    ((float4 *)h)[i] = v;
}

// ---------------------------------------------------------------------------
// Row softmax (in-place fp32) + emit bf16 hi/lo split of attn
// ---------------------------------------------------------------------------
__global__ void softmax_row(float *__restrict__ attn,
                            __nv_bfloat16 *__restrict__ ahi,
                            __nv_bfloat16 *__restrict__ alo)
{
    extern __shared__ float row[];
    __shared__ float red[256];
    const int t = threadIdx.x;
    float *p = attn + (size_t)blockIdx.x * NCELL;
    __nv_bfloat162 *ph = (__nv_bfloat162 *)(ahi + (size_t)blockIdx.x * NCELL);
    __nv_bfloat162 *pl = (__nv_bfloat162 *)(alo + (size_t)blockIdx.x * NCELL);

    float m = -1e30f;
    for (int i = t; i < NCELL / 4; i += 256) {
        float4 v = ((const float4 *)p)[i];
        ((float4 *)row)[i] = v;
        m = fmaxf(m, fmaxf(fmaxf(v.x, v.y), fmaxf(v.z, v.w)));
    }
    red[t] = m; __syncthreads();
    for (int s = 128; s > 0; s >>= 1) {
        if (t < s) red[t] = fmaxf(red[t], red[t + s]);
        __syncthreads();
    }
    const float bmax = red[0];
    __syncthreads();

    float sum = 0.f;
    for (int i = t; i < NCELL / 4; i += 256) {
        float4 v = ((float4 *)row)[i];
        v.x = __expf(v.x - bmax); v.y = __expf(v.y - bmax);
        v.z = __expf(v.z - bmax); v.w = __expf(v.w - bmax);
        sum += v.x + v.y + v.z + v.w;
        ((float4 *)row)[i] = v;
    }
    red[t] = sum; __syncthreads();
    for (int s = 128; s > 0; s >>= 1) {
        if (t < s) red[t] += red[t + s];
        __syncthreads();
    }
    const float inv = 1.f / red[0];
    __syncthreads();

    for (int i = t; i < NCELL / 4; i += 256) {
        float4 v = ((float4 *)row)[i];
        v.x *= inv; v.y *= inv; v.z *= inv; v.w *= inv;
        ((float4 *)p)[i] = v;
        __nv_bfloat16 h0, h1, h2, h3, l0, l1, l2, l3;
        split1(v.x, h0, l0); split1(v.y, h1, l1);
        split1(v.z, h2, l2); split1(v.w, h3, l3);
        ph[i * 2 + 0] = __nv_bfloat162(h0, h1);
        ph[i * 2 + 1] = __nv_bfloat162(h2, h3);
        pl[i * 2 + 0] = __nv_bfloat162(l0, l1);
        pl[i * 2 + 1] = __nv_bfloat162(l2, l3);
    }
}

// ---------------------------------------------------------------------------
// Variational heads
// ---------------------------------------------------------------------------
__global__ void heads_kernel(const float *__restrict__ o,
                             const float *__restrict__ mW, const float *__restrict__ mb,
                             const float *__restrict__ vW, const float *__restrict__ vb,
                             const float *__restrict__ eps,
                             float *__restrict__ qm, float *__restrict__ qv,
                             float *__restrict__ lat)
{
    extern __shared__ float sm[];
    float *Wm  = sm;
    float *Wv  = sm + 4096;
    float *osm = sm + 8192;
    const int t = threadIdx.x;
    const int r0 = blockIdx.x * 128;

    for (int i = t; i < HDIM * NOUTD; i += 256) { Wm[i] = mW[i]; Wv[i] = vW[i]; }
    for (int i = t; i < 128 * HDIM; i += 256) {
        int r = i >> 7, c = i & 127;
        osm[r * 129 + c] = o[(size_t)(r0 + r) * HDIM + c];
    }
    __syncthreads();

    for (int idx = t; idx < 128 * NOUTD; idx += 256) {
        int r = idx >> 5, c = idx & 31;
        const float *orow = &osm[r * 129];
        float dm = 0.f, dv = 0.f;
#pragma unroll 8
        for (int k = 0; k < HDIM; ++k) {
            float ov = orow[k];
            dm += ov * Wm[k * NOUTD + c];
            dv += ov * Wv[k * NOUTD + c];
        }
        int R = r0 + r;
        float mval = dm + mb[c];
        float vval = __expf(dv + vb[c]);
        qm[R * NOUTD + c]  = mval;
        qv[R * NOUTD + c]  = vval;
        lat[R * NOUTD + c] = mval + sqrtf(vval) * eps[R * NOUTD + c];
    }
}

// ---------------------------------------------------------------------------
// Launch
// ---------------------------------------------------------------------------
extern "C" void kernel_launch(void *const *d_in, const int *in_sizes, int n_in,
                              void *d_out, int out_size)
{
    const float *x       = (const float *)d_in[0];
    const float *spatial = (const float *)d_in[1];
    const float *eps     = (const float *)d_in[2];
    const float *enc_W   = (const float *)d_in[3];
    const float *enc_g   = (const float *)d_in[5];
    const float *enc_be  = (const float *)d_in[6];
    const float *sh_W1   = (const float *)d_in[7];
    const float *sh_g1   = (const float *)d_in[9];
    const float *sh_be1  = (const float *)d_in[10];
    const float *sh_W2   = (const float *)d_in[11];
    const float *sh_g2   = (const float *)d_in[13];
    const float *sh_be2  = (const float *)d_in[14];
    const float *qkv_W   = (const float *)d_in[15];
    const float *qkv_b   = (const float *)d_in[16];
    const float *o_W     = (const float *)d_in[17];
    const float *o_b     = (const float *)d_in[18];
    const float *mean_W  = (const float *)d_in[19];
    const float *mean_b  = (const float *)d_in[20];
    const float *var_W   = (const float *)d_in[21];
    const float *var_b   = (const float *)d_in[22];
    const int   *hid     = (const int *)d_in[23];

    float *out = (float *)d_out;
    float *out_qm   = out;
    float *out_qv   = out + (size_t)NCELL * NOUTD;
    float *out_lat  = out + 2 * (size_t)NCELL * NOUTD;
    float *out_attn = out + 3 * (size_t)NCELL * NOUTD;

    float *bufA, *bufB, *qkv, *kagg, *stats;
    __nv_bfloat16 *sp_hi, *sp_lo, *at_hi, *at_lo, *q_hi, *q_lo, *ka_hi, *ka_lo;
    __nv_bfloat16 *kT_hi, *kT_lo, *vT_hi, *vT_lo;
    cudaGetSymbolAddress((void **)&bufA, g_bufA);
    cudaGetSymbolAddress((void **)&bufB, g_bufB);
    cudaGetSymbolAddress((void **)&qkv,  g_qkv);
    cudaGetSymbolAddress((void **)&kagg, g_kagg);
    cudaGetSymbolAddress((void **)&stats, g_stats);
    cudaGetSymbolAddress((void **)&sp_hi, g_sp_hi);
    cudaGetSymbolAddress((void **)&sp_lo, g_sp_lo);
    cudaGetSymbolAddress((void **)&at_hi, g_at_hi);
    cudaGetSymbolAddress((void **)&at_lo, g_at_lo);
    cudaGetSymbolAddress((void **)&q_hi, g_q_hi);
    cudaGetSymbolAddress((void **)&q_lo, g_q_lo);
    cudaGetSymbolAddress((void **)&ka_hi, g_ka_hi);
    cudaGetSymbolAddress((void **)&ka_lo, g_ka_lo);
    cudaGetSymbolAddress((void **)&kT_hi, g_kT_hi);
    cudaGetSymbolAddress((void **)&kT_lo, g_kT_lo);
    cudaGetSymbolAddress((void **)&vT_hi, g_vT_hi);
    cudaGetSymbolAddress((void **)&vT_lo, g_vT_lo);

    cudaFuncSetAttribute(tc_gemm<true>,  cudaFuncAttributeMaxDynamicSharedMemorySize, SM_TOTAL);
    cudaFuncSetAttribute(tc_gemm<false>, cudaFuncAttributeMaxDynamicSharedMemorySize, SM_TOTAL);

    const size_t NH_BYTES = (size_t)NCELL * HDIM * sizeof(float);
    const float SCALE = 0.08838834764831845f; // 1/sqrt(128)

    // 1. head-specific encoder (bias cancels in BN)
    cudaMemsetAsync(bufA, 0, NH_BYTES);
    gemm_tile<false, true><<<dim3(64, 1, 4), 256>>>(
        x, enc_W, bufA, NINP, HDIM, HDIM, NINP, 1.f, nullptr, hid,
        (long long)NINP * HDIM);
    cudaMemsetAsync(stats, 0, 256 * sizeof(float));
    bn_stats<<<64, 128>>>(bufA, stats);
    bn_finalize<<<1, 128>>>(stats, enc_g, enc_be, hid, HDIM);
    bn_apply<<<1024, 256>>>(bufA, stats);

    // 2. shared layer 1
    cudaMemsetAsync(bufB, 0, NH_BYTES);
    gemm_tile<false, true><<<dim3(64, 1, 2), 256>>>(
        bufA, sh_W1, bufB, HDIM, HDIM, HDIM, HDIM, 1.f, nullptr, nullptr, 0);
    cudaMemsetAsync(stats, 0, 256 * sizeof(float));
    bn_stats<<<64, 128>>>(bufB, stats);
    bn_finalize<<<1, 128>>>(stats, sh_g1, sh_be1, nullptr, 0);
    bn_apply<<<1024, 256>>>(bufB, stats);

    // 3. shared layer 2
    cudaMemsetAsync(bufA, 0, NH_BYTES);
    gemm_tile<false, true><<<dim3(64, 1, 2), 256>>>(
        bufB, sh_W2, bufA, HDIM, HDIM, HDIM, HDIM, 1.f, nullptr, nullptr, 0);
    cudaMemsetAsync(stats, 0, 256 * sizeof(float));
    bn_stats<<<64, 128>>>(bufA, stats);
    bn_finalize<<<1, 128>>>(stats, sh_g2, sh_be2, nullptr, 0);
    bn_apply<<<1024, 256>>>(bufA, stats);

    // 4. qkv projection
    cudaMemsetAsync(qkv, 0, (size_t)NCELL * 3 * HDIM * sizeof(float));
    gemm_tile<false, true><<<dim3(64, 3, 2), 256>>>(
        bufA, qkv_W, qkv, HDIM, 3 * HDIM, 3 * HDIM, HDIM, 1.f, qkv_b, nullptr, 0);

    // 5. bf16 hi/lo conversions
    split_cols<<<65536, 256>>>(spatial, NCELL, 0, NCELL / 4, sp_hi, sp_lo);
    split_cols<<<1024, 256>>>(qkv, 3 * HDIM, 0, HDIM / 4, q_hi, q_lo);
    transpose_split<<<dim3(256, 4), dim3(32, 8)>>>(qkv, 3 * HDIM, HDIM, kT_hi, kT_lo);
    transpose_split<<<dim3(256, 4), dim3(32, 8)>>>(qkv, 3 * HDIM, 2 * HDIM, vT_hi, vT_lo);

    // 6. k_agg = spatial @ k    (tensor core, split-K=8, atomic fp32)
    cudaMemsetAsync(kagg, 0, NH_BYTES);
    tc_gemm<true><<<dim3(64, 1, 8), 128, SM_TOTAL>>>(
        sp_hi, sp_lo, NCELL, kT_hi, kT_lo, NCELL, kagg, HDIM, NCELL, 1.f);
    split_cols<<<1024, 256>>>(kagg, HDIM, 0, HDIM / 4, ka_hi, ka_lo);

    // 7. logits = (q @ k_agg^T) / sqrt(H)  -> out_attn
    tc_gemm<false><<<dim3(64, 64, 1), 128, SM_TOTAL>>>(
        q_hi, q_lo, HDIM, ka_hi, ka_lo, HDIM, out_attn, NCELL, HDIM, SCALE);

    // 8. softmax in place + bf16 split of attn
    softmax_row<<<NCELL, 256, NCELL * sizeof(float)>>>(out_attn, at_hi, at_lo);

    // 9. av = attn @ v   (tensor core, split-K=8, atomic fp32)
    cudaMemsetAsync(bufA, 0, NH_BYTES);
    tc_gemm<true><<<dim3(64, 1, 8), 128, SM_TOTAL>>>(
        at_hi, at_lo, NCELL, vT_hi, vT_lo, NCELL, bufA, HDIM, NCELL, 1.f);

    // 10. o = av @ o_W + o_b
    cudaMemsetAsync(bufB, 0, NH_BYTES);
    gemm_tile<false, true><<<dim3(64, 1, 2), 256>>>(
        bufA, o_W, bufB, HDIM, HDIM, HDIM, HDIM, 1.f, o_b, nullptr, 0);

    // 11. variational heads
    const int heads_smem = (4096 + 4096 + 128 * 129) * sizeof(float);
    cudaFuncSetAttribute(heads_kernel, cudaFuncAttributeMaxDynamicSharedMemorySize,
                         heads_smem);
    heads_kernel<<<64, 256, heads_smem>>>(bufB, mean_W, mean_b, var_W, var_b,
                                          eps, out_qm, out_qv, out_lat);
}

// round 4
// speedup vs baseline: 1.8785x; 1.8204x over previous
#include <cuda_runtime.h>
#include <cuda_bf16.h>
#include <math.h>
#include <stdint.h>

// ---------------------------------------------------------------------------
// Problem constants
// ---------------------------------------------------------------------------
#define NCELL 8192
#define NINP  2000
#define KPAD  2048
#define HDIM  128
#define NOUTD 32
#define BN_EPS 1e-3f

// fp32 GEMM tiling
#define BM 128
#define BN 128
#define BK 16

// tcgen05 only exists on the arch-specific (sm_103a) target; the harness also
// builds plain sm_103 — keep tcgen05 PTX out of that target.
#if defined(__CUDA_ARCH_FEAT_SM103_ALL) || defined(__CUDA_ARCH_FEAT_SM100_ALL) || \
    defined(__CUDA_ARCH_FEAT_SM110_ALL) || defined(__CUDA_ARCH_FEAT_SM101_ALL)
#define TC_ENABLED 1
#else
#define TC_ENABLED 0
#endif

// ---------------------------------------------------------------------------
// Scratch (static device buffers)
// ---------------------------------------------------------------------------
__device__ __align__(256) float g_bufA[NCELL * HDIM];
__device__ __align__(256) float g_bufB[NCELL * HDIM];
__device__ __align__(256) float g_qkv [NCELL * 3 * HDIM];
__device__ __align__(256) float g_kagg[NCELL * HDIM];
__device__ __align__(256) float g_stats[512];

__device__ __align__(256) __nv_bfloat16 g_sp_hi[(size_t)NCELL * NCELL];
__device__ __align__(256) __nv_bfloat16 g_sp_lo[(size_t)NCELL * NCELL];
__device__ __align__(256) __nv_bfloat16 g_at_hi[(size_t)NCELL * NCELL];
__device__ __align__(256) __nv_bfloat16 g_at_lo[(size_t)NCELL * NCELL];
__device__ __align__(256) __nv_bfloat16 g_q_hi [NCELL * HDIM];
__device__ __align__(256) __nv_bfloat16 g_q_lo [NCELL * HDIM];
__device__ __align__(256) __nv_bfloat16 g_ka_hi[NCELL * HDIM];
__device__ __align__(256) __nv_bfloat16 g_ka_lo[NCELL * HDIM];
__device__ __align__(256) __nv_bfloat16 g_kT_hi[HDIM * NCELL];
__device__ __align__(256) __nv_bfloat16 g_kT_lo[HDIM * NCELL];
__device__ __align__(256) __nv_bfloat16 g_vT_hi[HDIM * NCELL];
__device__ __align__(256) __nv_bfloat16 g_vT_lo[HDIM * NCELL];
__device__ __align__(256) __nv_bfloat16 g_x_hi [(size_t)NCELL * KPAD];
__device__ __align__(256) __nv_bfloat16 g_x_lo [(size_t)NCELL * KPAD];
__device__ __align__(256) __nv_bfloat16 g_wT_hi[HDIM * KPAD];
__device__ __align__(256) __nv_bfloat16 g_wT_lo[HDIM * KPAD];

// ---------------------------------------------------------------------------
// PTX helpers
// ---------------------------------------------------------------------------
__device__ __forceinline__ uint32_t cvta_smem(const void *p) {
    uint32_t a;
    asm("{ .reg .u64 t; cvta.to.shared.u64 t, %1; cvt.u32.u64 %0, t; }"
        : "=r"(a) : "l"(p));
    return a;
}
__device__ __forceinline__ uint32_t elect_one() {
    uint32_t p;
    asm volatile("{ .reg .pred p; elect.sync _|p, 0xFFFFFFFF; selp.b32 %0, 1, 0, p; }"
                 : "=r"(p));
    return p;
}
__device__ __forceinline__ void mbar_init(uint32_t mbar, uint32_t cnt) {
    asm volatile("mbarrier.init.shared.b64 [%0], %1;"
                 :: "r"(mbar), "r"(cnt) : "memory");
}
__device__ __forceinline__ void mbar_wait(uint32_t mbar, uint32_t parity) {
    asm volatile(
        "{\n\t.reg .pred P;\n"
        "LW_%=:\n\t"
        "mbarrier.try_wait.parity.acquire.cta.shared::cta.b64 P, [%0], %1, 0x989680;\n\t"
        "@P bra LD_%=;\n\t"
        "bra LW_%=;\n"
        "LD_%=:\n\t}"
        :: "r"(mbar), "r"(parity) : "memory");
}
__device__ __forceinline__ void fence_async_smem() {
    asm volatile("fence.proxy.async.shared::cta;" ::: "memory");
}
// cp.async (sm_80+, safe on both targets)
__device__ __forceinline__ void cpa16(uint32_t dst, const void *src) {
    asm volatile("cp.async.cg.shared.global [%0], [%1], 16;"
                 :: "r"(dst), "l"(src) : "memory");
}
__device__ __forceinline__ void cpa_commit() {
    asm volatile("cp.async.commit_group;" ::: "memory");
}
template <int N>
__device__ __forceinline__ void cpa_wait() {
    asm volatile("cp.async.wait_group %0;" :: "n"(N) : "memory");
}

// ---- tcgen05 helpers (referenced only inside TC_ENABLED bodies) ----
__device__ __forceinline__ void tc_alloc(uint32_t smem_dst, uint32_t ncols) {
    asm volatile("tcgen05.alloc.cta_group::1.sync.aligned.shared::cta.b32 [%0], %1;"
                 :: "r"(smem_dst), "r"(ncols) : "memory");
}
__device__ __forceinline__ void tc_dealloc(uint32_t tmem, uint32_t ncols) {
    asm volatile("tcgen05.dealloc.cta_group::1.sync.aligned.b32 %0, %1;"
                 :: "r"(tmem), "r"(ncols));
}
__device__ __forceinline__ void tc_relinquish() {
    asm volatile("tcgen05.relinquish_alloc_permit.cta_group::1.sync.aligned;");
}
__device__ __forceinline__ void tc_commit(uint32_t mbar) {
    asm volatile("tcgen05.commit.cta_group::1.mbarrier::arrive::one.shared::cluster.b64 [%0];"
                 :: "r"(mbar) : "memory");
}
__device__ __forceinline__ void tc_fence_after() {
    asm volatile("tcgen05.fence::after_thread_sync;" ::: "memory");
}
__device__ __forceinline__ void tc_wait_ld() {
    asm volatile("tcgen05.wait::ld.sync.aligned;" ::: "memory");
}
__device__ __forceinline__ void ldtm32(uint32_t *r, uint32_t addr) {
    asm volatile(
        "tcgen05.ld.sync.aligned.32x32b.x32.b32 "
        "{%0, %1, %2, %3, %4, %5, %6, %7, "
        " %8, %9, %10, %11, %12, %13, %14, %15, "
        " %16, %17, %18, %19, %20, %21, %22, %23, "
        " %24, %25, %26, %27, %28, %29, %30, %31}, [%32];"
        : "=r"(r[0]),  "=r"(r[1]),  "=r"(r[2]),  "=r"(r[3]),
          "=r"(r[4]),  "=r"(r[5]),  "=r"(r[6]),  "=r"(r[7]),
          "=r"(r[8]),  "=r"(r[9]),  "=r"(r[10]), "=r"(r[11]),
          "=r"(r[12]), "=r"(r[13]), "=r"(r[14]), "=r"(r[15]),
          "=r"(r[16]), "=r"(r[17]), "=r"(r[18]), "=r"(r[19]),
          "=r"(r[20]), "=r"(r[21]), "=r"(r[22]), "=r"(r[23]),
          "=r"(r[24]), "=r"(r[25]), "=r"(r[26]), "=r"(r[27]),
          "=r"(r[28]), "=r"(r[29]), "=r"(r[30]), "=r"(r[31])
        : "r"(addr));
}
__device__ __forceinline__ void mma_f16_ss(uint32_t d, uint64_t a_desc,
                                           uint64_t b_desc, uint32_t idesc,
                                           uint32_t en) {
    asm volatile(
        "{\n\t.reg .pred p;\n\t"
        "setp.ne.u32 p, %5, 0;\n\t"
        "tcgen05.mma.cta_group::1.kind::f16 [%0], %1, %2, %3, {%4, %4, %4, %4}, p;\n\t}"
        :: "r"(d), "l"(a_desc), "l"(b_desc), "r"(idesc), "r"(0u), "r"(en)
        : "memory");
}
__device__ __forceinline__ uint64_t make_desc(uint32_t addr) {
    return ((uint64_t)2 << 61) | ((uint64_t)1 << 46) | ((uint64_t)64 << 32) |
           ((uint64_t)1 << 16) | (((uint64_t)(addr >> 4)) & 0x3FFF);
}
__device__ __forceinline__ void fma2(float2 &c, const float2 &a, const float2 &b) {
    unsigned long long       &cc = reinterpret_cast<unsigned long long &>(c);
    const unsigned long long &aa = reinterpret_cast<const unsigned long long &>(a);
    const unsigned long long &bb = reinterpret_cast<const unsigned long long &>(b);
    asm("fma.rn.f32x2 %0, %1, %2, %0;" : "+l"(cc) : "l"(aa), "l"(bb));
}
__device__ __forceinline__ void split1(float v, __nv_bfloat16 &h, __nv_bfloat16 &l) {
    h = __float2bfloat16(v);
    l = __float2bfloat16(v - __bfloat162float(h));
}

static constexpr uint32_t TC_IDESC = 0x8200490u; // F32 acc, BF16xBF16, M=128, N=128

// swizzle offsets (SW128), 16B-chunk granularity
__device__ __forceinline__ uint32_t sw16(int r, int ch) {  // 128x64 bf16 tile (16KB)
    uint32_t byte = (r >> 3) * 1024 + (r & 7) * 128 + ch * 16;
    return byte ^ ((byte >> 3) & 0x70);
}
__device__ __forceinline__ uint32_t sw32(int r, int ch) {  // 128x128 bf16 tile (32KB)
    uint32_t byte = ((r >> 3) + (ch >> 3) * 16) * 1024 + (r & 7) * 128 + (ch & 7) * 16;
    return byte ^ ((byte >> 3) & 0x70);
}

// ---------------------------------------------------------------------------
// tc_skinny: C[128-mtile, 128] += alpha*(Ahi+Alo)[M,K] @ (Bhi+Blo)[128,K]^T
// split-K over gridDim.z; K=64 stages, cp.async double-buffered; atomic epilogue.
// smem: header 1KB + 2 x (4 x 16KB) = 132096
// ---------------------------------------------------------------------------
#define SKINNY_SMEM (1024 + 2 * 65536)

__global__ void __launch_bounds__(128)
tc_skinny(const __nv_bfloat16 *__restrict__ Ahi, const __nv_bfloat16 *__restrict__ Alo,
          int lda,
          const __nv_bfloat16 *__restrict__ Bhi, const __nv_bfloat16 *__restrict__ Blo,
          int ldb,
          float *__restrict__ C, int ldc, int K, float alpha)
{
#if TC_ENABLED
    extern __shared__ char sm[];
    const uint32_t sb = cvta_smem(sm);
    const int tid = threadIdx.x;
    const int wid = tid >> 5;

    if (wid == 0) tc_alloc(sb, 128);
    if (tid == 64) mbar_init(sb + 8, 1);
    __syncthreads();
    uint32_t tmem;
    asm volatile("ld.shared.b32 %0, [%1];" : "=r"(tmem) : "r"(sb));

    const int m0 = blockIdx.x * 128;
    const int n0 = blockIdx.y * 128;
    const int kpc = K / gridDim.z;
    const int S = kpc >> 6;
    const int kb0 = blockIdx.z * kpc;

    auto load_stage = [&](int s) {
        const uint32_t base = sb + 1024 + (s & 1) * 65536;
        const size_t kb = (size_t)kb0 + s * 64;
#pragma unroll
        for (int i = tid; i < 1024; i += 128) {
            int r = i >> 3, ch = i & 7;
            uint32_t so = sw16(r, ch);
            const __nv_bfloat16 *ap = Ahi + (size_t)(m0 + r) * lda + kb + ch * 8;
            const __nv_bfloat16 *al = Alo + (size_t)(m0 + r) * lda + kb + ch * 8;
            const __nv_bfloat16 *bp = Bhi + (size_t)(n0 + r) * ldb + kb + ch * 8;
            const __nv_bfloat16 *bl = Blo + (size_t)(n0 + r) * ldb + kb + ch * 8;
            cpa16(base + so,         ap);
            cpa16(base + 16384 + so, al);
            cpa16(base + 32768 + so, bp);
            cpa16(base + 49152 + so, bl);
        }
        cpa_commit();
    };

    load_stage(0);
    uint32_t ph = 0;
    for (int s = 0; s < S; ++s) {
        if (s + 1 < S) { load_stage(s + 1); cpa_wait<1>(); }
        else           { cpa_wait<0>(); }
        __syncthreads();
        fence_async_smem();
        if (wid == 0 && elect_one()) {
            const uint32_t base = sb + 1024 + (s & 1) * 65536;
            uint64_t dah = make_desc(base);
            uint64_t dal = make_desc(base + 16384);
            uint64_t dbh = make_desc(base + 32768);
            uint64_t dbl = make_desc(base + 49152);
#pragma unroll
            for (int k = 0; k < 4; ++k) {
                uint64_t off = (uint64_t)(k * 2);
                mma_f16_ss(tmem, dah + off, dbh + off, TC_IDESC, (s > 0) || (k > 0));
                mma_f16_ss(tmem, dah + off, dbl + off, TC_IDESC, 1u);
                mma_f16_ss(tmem, dal + off, dbh + off, TC_IDESC, 1u);
            }
            tc_commit(sb + 8);
        }
        mbar_wait(sb + 8, ph);
        ph ^= 1;
        __syncthreads();
    }

    tc_fence_after();
    const int row = tid;
#pragma unroll
    for (int part = 0; part < 4; ++part) {
        uint32_t d[32];
        ldtm32(d, tmem + part * 32);
        tc_wait_ld();
        float *cp = C + (size_t)(m0 + row) * ldc + n0 + part * 32;
#pragma unroll
        for (int c = 0; c < 32; ++c)
            atomicAdd(cp + c, __uint_as_float(d[c]) * alpha);
    }
    __syncthreads();
    if (wid == 0) {
        tc_relinquish();
        tc_dealloc(tmem, 128);
    }
#endif
}

// ---------------------------------------------------------------------------
// tc_wide: logits. C[128-mtile, 512-ngroup] = alpha*(Ahi+Alo)@(Bhi+Blo)^T
// A,B: [8192,128] bf16; K=128. 4 N-tiles per CTA (TMEM 512 cols), B double-buffered.
// smem: 1KB hdr + A 64KB + 2 x B 64KB = 197632
// ---------------------------------------------------------------------------
#define WIDE_SMEM (1024 + 65536 + 131072)

__global__ void __launch_bounds__(128)
tc_wide(const __nv_bfloat16 *__restrict__ Ahi, const __nv_bfloat16 *__restrict__ Alo,
        const __nv_bfloat16 *__restrict__ Bhi, const __nv_bfloat16 *__restrict__ Blo,
        float *__restrict__ C, float alpha)
{
#if TC_ENABLED
    extern __shared__ char sm[];
    const uint32_t sb = cvta_smem(sm);
    const int tid = threadIdx.x;
    const int wid = tid >> 5;

    if (wid == 0) tc_alloc(sb, 512);
    if (tid == 64) mbar_init(sb + 8, 1);
    __syncthreads();
    uint32_t tmem;
    asm volatile("ld.shared.b32 %0, [%1];" : "=r"(tmem) : "r"(sb));

    const int m0 = blockIdx.x * 128;
    const int ng0 = blockIdx.y * 512;

    const uint32_t A0 = sb + 1024;
    const uint32_t A1 = A0 + 32768;

    auto load_B = [&](int n) {
        const uint32_t base = sb + 1024 + 65536 + (n & 1) * 65536;
        const int r0 = ng0 + n * 128;
#pragma unroll
        for (int i = tid; i < 2048; i += 128) {
            int r = i >> 4, ch = i & 15;
            uint32_t so = sw32(r, ch);
            cpa16(base + so,         Bhi + (size_t)(r0 + r) * HDIM + ch * 8);
            cpa16(base + 32768 + so, Blo + (size_t)(r0 + r) * HDIM + ch * 8);
        }
        cpa_commit();
    };

    // prologue: A (hi+lo) + B(0), one group
#pragma unroll
    for (int i = tid; i < 2048; i += 128) {
        int r = i >> 4, ch = i & 15;
        uint32_t so = sw32(r, ch);
        cpa16(A0 + so, Ahi + (size_t)(m0 + r) * HDIM + ch * 8);
        cpa16(A1 + so, Alo + (size_t)(m0 + r) * HDIM + ch * 8);
    }
    {
        const uint32_t base = sb + 1024 + 65536;
        const int r0 = ng0;
#pragma unroll
        for (int i = tid; i < 2048; i += 128) {
            int r = i >> 4, ch = i & 15;
            uint32_t so = sw32(r, ch);
            cpa16(base + so,         Bhi + (size_t)(r0 + r) * HDIM + ch * 8);
            cpa16(base + 32768 + so, Blo + (size_t)(r0 + r) * HDIM + ch * 8);
        }
    }
    cpa_commit();

    uint32_t ph = 0;
    for (int n = 0; n < 4; ++n) {
        if (n + 1 < 4) { load_B(n + 1); cpa_wait<1>(); }
        else           { cpa_wait<0>(); }
        __syncthreads();
        fence_async_smem();
        if (wid == 0 && elect_one()) {
            const uint32_t bbase = sb + 1024 + 65536 + (n & 1) * 65536;
            uint64_t dah = make_desc(A0);
            uint64_t dal = make_desc(A1);
            uint64_t dbh = make_desc(bbase);
            uint64_t dbl = make_desc(bbase + 32768);
            const uint32_t acc = tmem + n * 128;
#pragma unroll
            for (int k = 0; k < 8; ++k) {
                uint64_t off = (uint64_t)((k & 3) * 2 + (k >> 2) * 1024);
                mma_f16_ss(acc, dah + off, dbh + off, TC_IDESC, k > 0);
                mma_f16_ss(acc, dah + off, dbl + off, TC_IDESC, 1u);
                mma_f16_ss(acc, dal + off, dbh + off, TC_IDESC, 1u);
            }
            tc_commit(sb + 8);
        }
        mbar_wait(sb + 8, ph);
        ph ^= 1;
        __syncthreads();
    }

    // epilogue: 4 n-tiles x 4 parts, smem-staged coalesced stores
    tc_fence_after();
    float *st = (float *)(sm + 1024);
    for (int n = 0; n < 4; ++n) {
#pragma unroll
        for (int part = 0; part < 4; ++part) {
            uint32_t d[32];
            ldtm32(d, tmem + n * 128 + part * 32);
            tc_wait_ld();
#pragma unroll
            for (int c = 0; c < 32; ++c)
                st[tid * 33 + c] = __uint_as_float(d[c]) * alpha;
            __syncthreads();
            const int col0 = ng0 + n * 128 + part * 32;
#pragma unroll
            for (int i = 0; i < 32; ++i) {
                int idx = i * 128 + tid;
                int rr = idx >> 5, cc = idx & 31;
                C[(size_t)(m0 + rr) * NCELL + col0 + cc] = st[rr * 33 + cc];
            }
            __syncthreads();
        }
    }
    __syncthreads();
    if (wid == 0) {
        tc_relinquish();
        tc_dealloc(tmem, 512);
    }
#endif
}

// ---------------------------------------------------------------------------
// fp32 -> bf16 hi/lo split kernels
// ---------------------------------------------------------------------------
__global__ void split_cols(const float *__restrict__ src, int ldsrc, int col0,
                           int cols4, __nv_bfloat16 *__restrict__ hi,
                           __nv_bfloat16 *__restrict__ lo)
{
    int idx = blockIdx.x * blockDim.x + threadIdx.x;
    int r = idx / cols4, c = idx - r * cols4;
    float4 v = *(const float4 *)(src + (size_t)r * ldsrc + col0 + c * 4);
    __nv_bfloat16 h0, h1, h2, h3, l0, l1, l2, l3;
    split1(v.x, h0, l0); split1(v.y, h1, l1);
    split1(v.z, h2, l2); split1(v.w, h3, l3);
    __nv_bfloat162 *ph = (__nv_bfloat162 *)(hi + (size_t)idx * 4);
    __nv_bfloat162 *pl = (__nv_bfloat162 *)(lo + (size_t)idx * 4);
    ph[0] = __nv_bfloat162(h0, h1); ph[1] = __nv_bfloat162(h2, h3);
    pl[0] = __nv_bfloat162(l0, l1); pl[1] = __nv_bfloat162(l2, l3);
}

// x [8192,2000] fp32 -> x_hi/x_lo [8192,2048] bf16 (zero-padded)
__global__ void x_split(const float *__restrict__ x,
                        __nv_bfloat16 *__restrict__ hi, __nv_bfloat16 *__restrict__ lo)
{
    int idx = blockIdx.x * blockDim.x + threadIdx.x;   // 8192*512
    int r = idx >> 9, c4 = idx & 511;
    float4 v = make_float4(0.f, 0.f, 0.f, 0.f);
    if (c4 < 500) v = *(const float4 *)(x + (size_t)r * NINP + c4 * 4);
    __nv_bfloat16 h0, h1, h2, h3, l0, l1, l2, l3;
    split1(v.x, h0, l0); split1(v.y, h1, l1);
    split1(v.z, h2, l2); split1(v.w, h3, l3);
    size_t o = ((size_t)r * KPAD + c4 * 4) >> 1;
    ((__nv_bfloat162 *)hi)[o + 0] = __nv_bfloat162(h0, h1);
    ((__nv_bfloat162 *)hi)[o + 1] = __nv_bfloat162(h2, h3);
    ((__nv_bfloat162 *)lo)[o + 0] = __nv_bfloat162(l0, l1);
    ((__nv_bfloat162 *)lo)[o + 1] = __nv_bfloat162(l2, l3);
}

// enc_W[hid] [2000,128] -> wT hi/lo [128,2048] (transposed, zero-padded)
__global__ void wT_split(const float *__restrict__ W, const int *__restrict__ hid,
                         __nv_bfloat16 *__restrict__ hi, __nv_bfloat16 *__restrict__ lo)
{
    int idx = blockIdx.x * blockDim.x + threadIdx.x;   // 128*2048
    int r = idx >> 7;        // k index 0..2047
    int c = idx & 127;       // output col 0..127
    const float *Wh = W + (size_t)hid[0] * NINP * HDIM;
    float v = (r < NINP) ? Wh[(size_t)r * HDIM + c] : 0.f;
    __nv_bfloat16 h, l;
    split1(v, h, l);
    size_t o = (size_t)c * KPAD + r;
    hi[o] = h;
    lo[o] = l;
}

// transpose + split: dst[c, r] = src[r, col0 + c], dst is [128, NCELL]
__global__ void transpose_split(const float *__restrict__ src, int ldsrc, int col0,
                                __nv_bfloat16 *__restrict__ hi,
                                __nv_bfloat16 *__restrict__ lo)
{
    __shared__ float t[32][33];
    int r0 = blockIdx.x * 32, c0 = blockIdx.y * 32;
    int tx = threadIdx.x, ty = threadIdx.y;  // 32 x 8
#pragma unroll
    for (int i = 0; i < 4; ++i) {
        int r = ty + i * 8;
        t[r][tx] = src[(size_t)(r0 + r) * ldsrc + col0 + c0 + tx];
    }
    __syncthreads();
#pragma unroll
    for (int i = 0; i < 4; ++i) {
        int c = ty + i * 8;
        float v = t[tx][c];
        __nv_bfloat16 h, l;
        split1(v, h, l);
        size_t o = (size_t)(c0 + c) * NCELL + r0 + tx;
        hi[o] = h;
        lo[o] = l;
    }
}

// ---------------------------------------------------------------------------
// fp32 tiled SGEMM (small GEMMs): C = alpha*A@B (+bias), split-K atomics
// ---------------------------------------------------------------------------
template <bool NT, bool ATOMIC>
__global__ void __launch_bounds__(256)
gemm_tile(const float *__restrict__ A, const float *__restrict__ Bbase,
          float *__restrict__ C,
          int lda, int ldb, int ldc, int K,
          float alpha, const float *__restrict__ bias,
          const int *__restrict__ hid, long long headStride)
{
    const float *B = Bbase + (hid ? (long long)hid[0] * headStride : 0);

    __shared__ float As[BK][BM + 4];
    __shared__ float Bs[BK][BN + 4];

    const int tid = threadIdx.x;
    const int tx = tid & 15;
    const int ty = tid >> 4;
    const int m0 = blockIdx.x * BM;
    const int n0 = blockIdx.y * BN;

    const int chunks = K / BK;
    const int nz = gridDim.z, z = blockIdx.z;
    const int per = chunks / nz, rem = chunks % nz;
    const int c0 = z * per + (z < rem ? z : rem);
    const int c1 = c0 + per + (z < rem ? 1 : 0);

    const int f0 = tid, f1 = tid + 256;
    const int aRow0 = f0 >> 2, aK0 = (f0 & 3) * 4;
    const int aRow1 = f1 >> 2, aK1 = (f1 & 3) * 4;
    const int bK0 = f0 >> 5, bN0 = (f0 & 31) * 4;
    const int bK1 = f1 >> 5, bN1 = (f1 & 31) * 4;

    const float *Ap0 = A + (size_t)(m0 + aRow0) * lda + (size_t)c0 * BK + aK0;
    const float *Ap1 = A + (size_t)(m0 + aRow1) * lda + (size_t)c0 * BK + aK1;
    const float *Bp0, *Bp1;
    if (NT) {
        Bp0 = B + (size_t)(n0 + aRow0) * ldb + (size_t)c0 * BK + aK0;
        Bp1 = B + (size_t)(n0 + aRow1) * ldb + (size_t)c0 * BK + aK1;
    } else {
        Bp0 = B + (size_t)(c0 * BK + bK0) * ldb + n0 + bN0;
        Bp1 = B + (size_t)(c0 * BK + bK1) * ldb + n0 + bN1;
    }

    float2 acc[8][4];
#pragma unroll
    for (int i = 0; i < 8; ++i)
#pragma unroll
        for (int j = 0; j < 4; ++j) acc[i][j] = make_float2(0.f, 0.f);

    float4 ra0 = *(const float4 *)Ap0;
    float4 ra1 = *(const float4 *)Ap1;
    float4 rb0 = *(const float4 *)Bp0;
    float4 rb1 = *(const float4 *)Bp1;

    for (int c = c0; c < c1; ++c) {
        __syncthreads();
        As[aK0 + 0][aRow0] = ra0.x; As[aK0 + 1][aRow0] = ra0.y;
        As[aK0 + 2][aRow0] = ra0.z; As[aK0 + 3][aRow0] = ra0.w;
        As[aK1 + 0][aRow1] = ra1.x; As[aK1 + 1][aRow1] = ra1.y;
        As[aK1 + 2][aRow1] = ra1.z; As[aK1 + 3][aRow1] = ra1.w;
        if (NT) {
            Bs[aK0 + 0][aRow0] = rb0.x; Bs[aK0 + 1][aRow0] = rb0.y;
            Bs[aK0 + 2][aRow0] = rb0.z; Bs[aK0 + 3][aRow0] = rb0.w;
            Bs[aK1 + 0][aRow1] = rb1.x; Bs[aK1 + 1][aRow1] = rb1.y;
            Bs[aK1 + 2][aRow1] = rb1.z; Bs[aK1 + 3][aRow1] = rb1.w;
        } else {
            *(float4 *)&Bs[bK0][bN0] = rb0;
            *(float4 *)&Bs[bK1][bN1] = rb1;
        }
        __syncthreads();

        if (c + 1 < c1) {
            Ap0 += BK; Ap1 += BK;
            ra0 = *(const float4 *)Ap0;
            ra1 = *(const float4 *)Ap1;
            if (NT) {
                Bp0 += BK; Bp1 += BK;
            } else {
                Bp0 += (size_t)BK * ldb; Bp1 += (size_t)BK * ldb;
            }
            rb0 = *(const float4 *)Bp0;
            rb1 = *(const float4 *)Bp1;
        }

#pragma unroll
        for (int kk = 0; kk < BK; ++kk) {
            float4 a0 = *(const float4 *)&As[kk][ty * 4];
            float4 a1 = *(const float4 *)&As[kk][64 + ty * 4];
            float4 b0 = *(const float4 *)&Bs[kk][tx * 4];
            float4 b1 = *(const float4 *)&Bs[kk][64 + tx * 4];
            float av[8] = {a0.x, a0.y, a0.z, a0.w, a1.x, a1.y, a1.z, a1.w};
            float2 bp[4] = {make_float2(b0.x, b0.y), make_float2(b0.z, b0.w),
                            make_float2(b1.x, b1.y), make_float2(b1.z, b1.w)};
#pragma unroll
            for (int i = 0; i < 8; ++i) {
                float2 aa = make_float2(av[i], av[i]);
#pragma unroll
                for (int j = 0; j < 4; ++j) fma2(acc[i][j], aa, bp[j]);
            }
        }
    }

    float bad0[4] = {0.f, 0.f, 0.f, 0.f}, bad1[4] = {0.f, 0.f, 0.f, 0.f};
    if (bias != nullptr && blockIdx.z == 0) {
#pragma unroll
        for (int j = 0; j < 4; ++j) {
            bad0[j] = bias[n0 + tx * 4 + j];
            bad1[j] = bias[n0 + 64 + tx * 4 + j];
        }
    }
#pragma unroll
    for (int i = 0; i < 8; ++i) {
        int r = m0 + ((i < 4) ? (ty * 4 + i) : (64 + ty * 4 + (i - 4)));
        float v[8] = {acc[i][0].x, acc[i][0].y, acc[i][1].x, acc[i][1].y,
                      acc[i][2].x, acc[i][2].y, acc[i][3].x, acc[i][3].y};
        float *crow = C + (size_t)r * ldc;
        if (ATOMIC) {
#pragma unroll
            for (int j = 0; j < 4; ++j)
                atomicAdd(crow + n0 + tx * 4 + j, v[j] * alpha + bad0[j]);
#pragma unroll
            for (int j = 0; j < 4; ++j)
                atomicAdd(crow + n0 + 64 + tx * 4 + j, v[4 + j] * alpha + bad1[j]);
        } else {
            float4 w0 = make_float4(v[0] * alpha + bad0[0], v[1] * alpha + bad0[1],
                                    v[2] * alpha + bad0[2], v[3] * alpha + bad0[3]);
            float4 w1 = make_float4(v[4] * alpha + bad1[0], v[5] * alpha + bad1[1],
                                    v[6] * alpha + bad1[2], v[7] * alpha + bad1[3]);
            *(float4 *)(crow + n0 + tx * 4) = w0;
            *(float4 *)(crow + n0 + 64 + tx * 4) = w1;
        }
    }
}

// ---------------------------------------------------------------------------
// BatchNorm (training-mode) + ReLU
// ---------------------------------------------------------------------------
__global__ void bn_stats(const float *__restrict__ h, float *__restrict__ stats)
{
    int col = threadIdx.x;
    int r0 = blockIdx.x * 128;
    float s = 0.f, s2 = 0.f;
    for (int r = 0; r < 128; ++r) {
        float v = h[(size_t)(r0 + r) * HDIM + col];
        s += v; s2 += v * v;
    }
    atomicAdd(&stats[col], s);
    atomicAdd(&stats[128 + col], s2);
}

__global__ void bn_finalize(float *__restrict__ stats,
                            const float *__restrict__ g, const float *__restrict__ be,
                            const int *__restrict__ hid, int headStride)
{
    int c = threadIdx.x;
    int off = hid ? hid[0] * headStride : 0;
    float mean = stats[c] * (1.f / (float)NCELL);
    float var = stats[128 + c] * (1.f / (float)NCELL) - mean * mean;
    float rstd = rsqrtf(var + BN_EPS);
    float gg = g[off + c];
    stats[256 + c] = gg * rstd;
    stats[384 + c] = be[off + c] - gg * mean * rstd;
}

__global__ void bn_apply(float *__restrict__ h, const float *__restrict__ stats)
{
    const float *scale = stats + 256;
    const float *shift = stats + 384;
    int i = blockIdx.x * blockDim.x + threadIdx.x;
    float4 v = ((float4 *)h)[i];
    int c = (i * 4) & (HDIM - 1);
    v.x = fmaxf(v.x * scale[c + 0] + shift[c + 0], 0.f);
    v.y = fmaxf(v.y * scale[c + 1] + shift[c + 1], 0.f);
    v.z = fmaxf(v.z * scale[c + 2] + shift[c + 2], 0.f);
    v.w = fmaxf(v.w * scale[c + 3] + shift[c + 3], 0.f);
    ((float4 *)h)[i] = v;
}

// ---------------------------------------------------------------------------
// Row softmax (in-place fp32) + bf16 hi/lo split of attn
// ---------------------------------------------------------------------------
__global__ void softmax_row(float *__restrict__ attn,
                            __nv_bfloat16 *__restrict__ ahi,
                            __nv_bfloat16 *__restrict__ alo)
{
    extern __shared__ float row[];
    __shared__ float red[256];
    const int t = threadIdx.x;
    float *p = attn + (size_t)blockIdx.x * NCELL;
    __nv_bfloat162 *ph = (__nv_bfloat162 *)(ahi + (size_t)blockIdx.x * NCELL);
    __nv_bfloat162 *pl = (__nv_bfloat162 *)(alo + (size_t)blockIdx.x * NCELL);

    float m = -1e30f;
    for (int i = t; i < NCELL / 4; i += 256) {
        float4 v = ((const float4 *)p)[i];
        ((float4 *)row)[i] = v;
        m = fmaxf(m, fmaxf(fmaxf(v.x, v.y), fmaxf(v.z, v.w)));
    }
    red[t] = m; __syncthreads();
    for (int s = 128; s > 0; s >>= 1) {
        if (t < s) red[t] = fmaxf(red[t], red[t + s]);
        __syncthreads();
    }
    const float bmax = red[0];
    __syncthreads();

    float sum = 0.f;
    for (int i = t; i < NCELL / 4; i += 256) {
        float4 v = ((float4 *)row)[i];
        v.x = __expf(v.x - bmax); v.y = __expf(v.y - bmax);
        v.z = __expf(v.z - bmax); v.w = __expf(v.w - bmax);
        sum += v.x + v.y + v.z + v.w;
        ((float4 *)row)[i] = v;
    }
    red[t] = sum; __syncthreads();
    for (int s = 128; s > 0; s >>= 1) {
        if (t < s) red[t] += red[t + s];
        __syncthreads();
    }
    const float inv = 1.f / red[0];
    __syncthreads();

    for (int i = t; i < NCELL / 4; i += 256) {
        float4 v = ((float4 *)row)[i];
        v.x *= inv; v.y *= inv; v.z *= inv; v.w *= inv;
        ((float4 *)p)[i] = v;
        __nv_bfloat16 h0, h1, h2, h3, l0, l1, l2, l3;
        split1(v.x, h0, l0); split1(v.y, h1, l1);
        split1(v.z, h2, l2); split1(v.w, h3, l3);
        ph[i * 2 + 0] = __nv_bfloat162(h0, h1);
        ph[i * 2 + 1] = __nv_bfloat162(h2, h3);
        pl[i * 2 + 0] = __nv_bfloat162(l0, l1);
        pl[i * 2 + 1] = __nv_bfloat162(l2, l3);
    }
}

// ---------------------------------------------------------------------------
// Variational heads
// ---------------------------------------------------------------------------
__global__ void heads_kernel(const float *__restrict__ o,
                             const float *__restrict__ mW, const float *__restrict__ mb,
                             const float *__restrict__ vW, const float *__restrict__ vb,
                             const float *__restrict__ eps,
                             float *__restrict__ qm, float *__restrict__ qv,
                             float *__restrict__ lat)
{
    extern __shared__ float smh[];
    float *Wm  = smh;
    float *Wv  = smh + 4096;
    float *osm = smh + 8192;
    const int t = threadIdx.x;
    const int r0 = blockIdx.x * 128;

    for (int i = t; i < HDIM * NOUTD; i += 256) { Wm[i] = mW[i]; Wv[i] = vW[i]; }
    for (int i = t; i < 128 * HDIM; i += 256) {
        int r = i >> 7, c = i & 127;
        osm[r * 129 + c] = o[(size_t)(r0 + r) * HDIM + c];
    }
    __syncthreads();

    for (int idx = t; idx < 128 * NOUTD; idx += 256) {
        int r = idx >> 5, c = idx & 31;
        const float *orow = &osm[r * 129];
        float dm = 0.f, dv = 0.f;
#pragma unroll 8
        for (int k = 0; k < HDIM; ++k) {
            float ov = orow[k];
            dm += ov * Wm[k * NOUTD + c];
            dv += ov * Wv[k * NOUTD + c];
        }
        int R = r0 + r;
        float mval = dm + mb[c];
        float vval = __expf(dv + vb[c]);
        qm[R * NOUTD + c]  = mval;
        qv[R * NOUTD + c]  = vval;
        lat[R * NOUTD + c] = mval + sqrtf(vval) * eps[R * NOUTD + c];
    }
}

// ---------------------------------------------------------------------------
// Launch
// ---------------------------------------------------------------------------
extern "C" void kernel_launch(void *const *d_in, const int *in_sizes, int n_in,
                              void *d_out, int out_size)
{
    const float *x       = (const float *)d_in[0];
    const float *spatial = (const float *)d_in[1];
    const float *eps     = (const float *)d_in[2];
    const float *enc_W   = (const float *)d_in[3];
    const float *enc_g   = (const float *)d_in[5];
    const float *enc_be  = (const float *)d_in[6];
    const float *sh_W1   = (const float *)d_in[7];
    const float *sh_g1   = (const float *)d_in[9];
    const float *sh_be1  = (const float *)d_in[10];
    const float *sh_W2   = (const float *)d_in[11];
    const float *sh_g2   = (const float *)d_in[13];
    const float *sh_be2  = (const float *)d_in[14];
    const float *qkv_W   = (const float *)d_in[15];
    const float *qkv_b   = (const float *)d_in[16];
    const float *o_W     = (const float *)d_in[17];
    const float *o_b     = (const float *)d_in[18];
    const float *mean_W  = (const float *)d_in[19];
    const float *mean_b  = (const float *)d_in[20];
    const float *var_W   = (const float *)d_in[21];
    const float *var_b   = (const float *)d_in[22];
    const int   *hid     = (const int *)d_in[23];

    float *out = (float *)d_out;
    float *out_qm   = out;
    float *out_qv   = out + (size_t)NCELL * NOUTD;
    float *out_lat  = out + 2 * (size_t)NCELL * NOUTD;
    float *out_attn = out + 3 * (size_t)NCELL * NOUTD;

    float *bufA, *bufB, *qkv, *kagg, *stats;
    __nv_bfloat16 *sp_hi, *sp_lo, *at_hi, *at_lo, *q_hi, *q_lo, *ka_hi, *ka_lo;
    __nv_bfloat16 *kT_hi, *kT_lo, *vT_hi, *vT_lo, *x_hi, *x_lo, *wT_hi, *wT_lo;
    cudaGetSymbolAddress((void **)&bufA, g_bufA);
    cudaGetSymbolAddress((void **)&bufB, g_bufB);
    cudaGetSymbolAddress((void **)&qkv,  g_qkv);
    cudaGetSymbolAddress((void **)&kagg, g_kagg);
    cudaGetSymbolAddress((void **)&stats, g_stats);
    cudaGetSymbolAddress((void **)&sp_hi, g_sp_hi);
    cudaGetSymbolAddress((void **)&sp_lo, g_sp_lo);
    cudaGetSymbolAddress((void **)&at_hi, g_at_hi);
    cudaGetSymbolAddress((void **)&at_lo, g_at_lo);
    cudaGetSymbolAddress((void **)&q_hi, g_q_hi);
    cudaGetSymbolAddress((void **)&q_lo, g_q_lo);
    cudaGetSymbolAddress((void **)&ka_hi, g_ka_hi);
    cudaGetSymbolAddress((void **)&ka_lo, g_ka_lo);
    cudaGetSymbolAddress((void **)&kT_hi, g_kT_hi);
    cudaGetSymbolAddress((void **)&kT_lo, g_kT_lo);
    cudaGetSymbolAddress((void **)&vT_hi, g_vT_hi);
    cudaGetSymbolAddress((void **)&vT_lo, g_vT_lo);
    cudaGetSymbolAddress((void **)&x_hi, g_x_hi);
    cudaGetSymbolAddress((void **)&x_lo, g_x_lo);
    cudaGetSymbolAddress((void **)&wT_hi, g_wT_hi);
    cudaGetSymbolAddress((void **)&wT_lo, g_wT_lo);

    cudaFuncSetAttribute(tc_skinny, cudaFuncAttributeMaxDynamicSharedMemorySize, SKINNY_SMEM);
    cudaFuncSetAttribute(tc_wide,   cudaFuncAttributeMaxDynamicSharedMemorySize, WIDE_SMEM);

    const size_t NH_BYTES = (size_t)NCELL * HDIM * sizeof(float);
    const float SCALE = 0.08838834764831845f; // 1/sqrt(128)

    // 1. encoder input conversions + tensor-core enc GEMM (bias cancels in BN)
    x_split<<<16384, 256>>>(x, x_hi, x_lo);
    wT_split<<<1024, 256>>>(enc_W, hid, wT_hi, wT_lo);
    cudaMemsetAsync(bufA, 0, NH_BYTES);
    tc_skinny<<<dim3(64, 1, 8), 128, SKINNY_SMEM>>>(
        x_hi, x_lo, KPAD, wT_hi, wT_lo, KPAD, bufA, HDIM, KPAD, 1.f);
    cudaMemsetAsync(stats, 0, 256 * sizeof(float));
    bn_stats<<<64, 128>>>(bufA, stats);
    bn_finalize<<<1, 128>>>(stats, enc_g, enc_be, hid, HDIM);
    bn_apply<<<1024, 256>>>(bufA, stats);

    // 2. shared layer 1
    cudaMemsetAsync(bufB, 0, NH_BYTES);
    gemm_tile<false, true><<<dim3(64, 1, 2), 256>>>(
        bufA, sh_W1, bufB, HDIM, HDIM, HDIM, HDIM, 1.f, nullptr, nullptr, 0);
    cudaMemsetAsync(stats, 0, 256 * sizeof(float));
    bn_stats<<<64, 128>>>(bufB, stats);
    bn_finalize<<<1, 128>>>(stats, sh_g1, sh_be1, nullptr, 0);
    bn_apply<<<1024, 256>>>(bufB, stats);

    // 3. shared layer 2
    cudaMemsetAsync(bufA, 0, NH_BYTES);
    gemm_tile<false, true><<<dim3(64, 1, 2), 256>>>(
        bufB, sh_W2, bufA, HDIM, HDIM, HDIM, HDIM, 1.f, nullptr, nullptr, 0);
    cudaMemsetAsync(stats, 0, 256 * sizeof(float));
    bn_stats<<<64, 128>>>(bufA, stats);
    bn_finalize<<<1, 128>>>(stats, sh_g2, sh_be2, nullptr, 0);
    bn_apply<<<1024, 256>>>(bufA, stats);

    // 4. qkv projection
    cudaMemsetAsync(qkv, 0, (size_t)NCELL * 3 * HDIM * sizeof(float));
    gemm_tile<false, true><<<dim3(64, 3, 2), 256>>>(
        bufA, qkv_W, qkv, HDIM, 3 * HDIM, 3 * HDIM, HDIM, 1.f, qkv_b, nullptr, 0);

    // 5. bf16 hi/lo conversions
    split_cols<<<65536, 256>>>(spatial, NCELL, 0, NCELL / 4, sp_hi, sp_lo);
    split_cols<<<1024, 256>>>(qkv, 3 * HDIM, 0, HDIM / 4, q_hi, q_lo);
    transpose_split<<<dim3(256, 4), dim3(32, 8)>>>(qkv, 3 * HDIM, HDIM, kT_hi, kT_lo);
    transpose_split<<<dim3(256, 4), dim3(32, 8)>>>(qkv, 3 * HDIM, 2 * HDIM, vT_hi, vT_lo);

    // 6. k_agg = spatial @ k
    cudaMemsetAsync(kagg, 0, NH_BYTES);
    tc_skinny<<<dim3(64, 1, 8), 128, SKINNY_SMEM>>>(
        sp_hi, sp_lo, NCELL, kT_hi, kT_lo, NCELL, kagg, HDIM, NCELL, 1.f);
    split_cols<<<1024, 256>>>(kagg, HDIM, 0, HDIM / 4, ka_hi, ka_lo);

    // 7. logits = (q @ k_agg^T) / sqrt(H)  -> out_attn
    tc_wide<<<dim3(64, 16), 128, WIDE_SMEM>>>(q_hi, q_lo, ka_hi, ka_lo, out_attn, SCALE);

    // 8. softmax in place + bf16 split of attn
    softmax_row<<<NCELL, 256, NCELL * sizeof(float)>>>(out_attn, at_hi, at_lo);

    // 9. av = attn @ v
    cudaMemsetAsync(bufA, 0, NH_BYTES);
    tc_skinny<<<dim3(64, 1, 8), 128, SKINNY_SMEM>>>(
        at_hi, at_lo, NCELL, vT_hi, vT_lo, NCELL, bufA, HDIM, NCELL, 1.f);

    // 10. o = av @ o_W + o_b
    cudaMemsetAsync(bufB, 0, NH_BYTES);
    gemm_tile<false, true><<<dim3(64, 1, 2), 256>>>(
        bufA, o_W, bufB, HDIM, HDIM, HDIM, HDIM, 1.f, o_b, nullptr, 0);

    // 11. variational heads
    const int heads_smem = (4096 + 4096 + 128 * 129) * sizeof(float);
    cudaFuncSetAttribute(heads_kernel, cudaFuncAttributeMaxDynamicSharedMemorySize,
                         heads_smem);
    heads_kernel<<<64, 256, heads_smem>>>(bufB, mean_W, mean_b, var_W, var_b,
                                          eps, out_qm, out_qv, out_lat);
}

// round 5
// speedup vs baseline: 2.1938x; 1.1678x over previous
#include <cuda_runtime.h>
#include <cuda_bf16.h>
#include <math.h>
#include <stdint.h>

// ---------------------------------------------------------------------------
// Problem constants
// ---------------------------------------------------------------------------
#define NCELL 8192
#define NINP  2000
#define KPAD  2048
#define HDIM  128
#define NOUTD 32
#define BN_EPS 1e-3f

#define BM 128
#define BN 128
#define BK 16

// tcgen05 exists only on the arch-specific target; harness also builds sm_103.
#if defined(__CUDA_ARCH_FEAT_SM103_ALL) || defined(__CUDA_ARCH_FEAT_SM100_ALL) || \
    defined(__CUDA_ARCH_FEAT_SM110_ALL) || defined(__CUDA_ARCH_FEAT_SM101_ALL)
#define TC_ENABLED 1
#else
#define TC_ENABLED 0
#endif

// ---------------------------------------------------------------------------
// Scratch
// ---------------------------------------------------------------------------
__device__ __align__(256) float g_bufA[NCELL * HDIM];
__device__ __align__(256) float g_bufB[NCELL * HDIM];
__device__ __align__(256) float g_qkv [NCELL * 3 * HDIM];
__device__ __align__(256) float g_kagg[NCELL * HDIM];
__device__ __align__(256) float g_stats[512];

__device__ __align__(256) __nv_bfloat16 g_q_hi [NCELL * HDIM];
__device__ __align__(256) __nv_bfloat16 g_q_lo [NCELL * HDIM];
__device__ __align__(256) __nv_bfloat16 g_ka_hi[NCELL * HDIM];
__device__ __align__(256) __nv_bfloat16 g_ka_lo[NCELL * HDIM];
__device__ __align__(256) __nv_bfloat16 g_kT_hi[HDIM * NCELL];
__device__ __align__(256) __nv_bfloat16 g_kT_lo[HDIM * NCELL];
__device__ __align__(256) __nv_bfloat16 g_vT_hi[HDIM * NCELL];
__device__ __align__(256) __nv_bfloat16 g_vT_lo[HDIM * NCELL];
__device__ __align__(256) __nv_bfloat16 g_wT_hi[HDIM * KPAD];
__device__ __align__(256) __nv_bfloat16 g_wT_lo[HDIM * KPAD];

// ---------------------------------------------------------------------------
// PTX helpers
// ---------------------------------------------------------------------------
__device__ __forceinline__ uint32_t cvta_smem(const void *p) {
    uint32_t a;
    asm("{ .reg .u64 t; cvta.to.shared.u64 t, %1; cvt.u32.u64 %0, t; }"
        : "=r"(a) : "l"(p));
    return a;
}
__device__ __forceinline__ uint32_t elect_one() {
    uint32_t p;
    asm volatile("{ .reg .pred p; elect.sync _|p, 0xFFFFFFFF; selp.b32 %0, 1, 0, p; }"
                 : "=r"(p));
    return p;
}
__device__ __forceinline__ void mbar_init(uint32_t mbar, uint32_t cnt) {
    asm volatile("mbarrier.init.shared.b64 [%0], %1;"
                 :: "r"(mbar), "r"(cnt) : "memory");
}
__device__ __forceinline__ void mbar_wait(uint32_t mbar, uint32_t parity) {
    asm volatile(
        "{\n\t.reg .pred P;\n"
        "LW_%=:\n\t"
        "mbarrier.try_wait.parity.acquire.cta.shared::cta.b64 P, [%0], %1, 0x989680;\n\t"
        "@P bra LD_%=;\n\t"
        "bra LW_%=;\n"
        "LD_%=:\n\t}"
        :: "r"(mbar), "r"(parity) : "memory");
}
__device__ __forceinline__ void fence_async_smem() {
    asm volatile("fence.proxy.async.shared::cta;" ::: "memory");
}
__device__ __forceinline__ void cpa16(uint32_t dst, const void *src) {
    asm volatile("cp.async.cg.shared.global [%0], [%1], 16;"
                 :: "r"(dst), "l"(src) : "memory");
}
__device__ __forceinline__ void cpa_commit() {
    asm volatile("cp.async.commit_group;" ::: "memory");
}
template <int N>
__device__ __forceinline__ void cpa_wait() {
    asm volatile("cp.async.wait_group %0;" :: "n"(N) : "memory");
}
// Vector fp32 reduction (sm_90+): 1 instruction instead of 4 scalar atomics
__device__ __forceinline__ void red4(float *p, float a, float b, float c, float d) {
    asm volatile("red.global.add.v4.f32 [%0], {%1, %2, %3, %4};"
                 :: "l"(p), "f"(a), "f"(b), "f"(c), "f"(d) : "memory");
}

// ---- tcgen05 helpers ----
__device__ __forceinline__ void tc_alloc(uint32_t smem_dst, uint32_t ncols) {
    asm volatile("tcgen05.alloc.cta_group::1.sync.aligned.shared::cta.b32 [%0], %1;"
                 :: "r"(smem_dst), "r"(ncols) : "memory");
}
__device__ __forceinline__ void tc_dealloc(uint32_t tmem, uint32_t ncols) {
    asm volatile("tcgen05.dealloc.cta_group::1.sync.aligned.b32 %0, %1;"
                 :: "r"(tmem), "r"(ncols));
}
__device__ __forceinline__ void tc_relinquish() {
    asm volatile("tcgen05.relinquish_alloc_permit.cta_group::1.sync.aligned;");
}
__device__ __forceinline__ void tc_commit(uint32_t mbar) {
    asm volatile("tcgen05.commit.cta_group::1.mbarrier::arrive::one.shared::cluster.b64 [%0];"
                 :: "r"(mbar) : "memory");
}
__device__ __forceinline__ void tc_fence_after() {
    asm volatile("tcgen05.fence::after_thread_sync;" ::: "memory");
}
__device__ __forceinline__ void tc_wait_ld() {
    asm volatile("tcgen05.wait::ld.sync.aligned;" ::: "memory");
}
__device__ __forceinline__ void ldtm32(uint32_t *r, uint32_t addr) {
    asm volatile(
        "tcgen05.ld.sync.aligned.32x32b.x32.b32 "
        "{%0, %1, %2, %3, %4, %5, %6, %7, "
        " %8, %9, %10, %11, %12, %13, %14, %15, "
        " %16, %17, %18, %19, %20, %21, %22, %23, "
        " %24, %25, %26, %27, %28, %29, %30, %31}, [%32];"
        : "=r"(r[0]),  "=r"(r[1]),  "=r"(r[2]),  "=r"(r[3]),
          "=r"(r[4]),  "=r"(r[5]),  "=r"(r[6]),  "=r"(r[7]),
          "=r"(r[8]),  "=r"(r[9]),  "=r"(r[10]), "=r"(r[11]),
          "=r"(r[12]), "=r"(r[13]), "=r"(r[14]), "=r"(r[15]),
          "=r"(r[16]), "=r"(r[17]), "=r"(r[18]), "=r"(r[19]),
          "=r"(r[20]), "=r"(r[21]), "=r"(r[22]), "=r"(r[23]),
          "=r"(r[24]), "=r"(r[25]), "=r"(r[26]), "=r"(r[27]),
          "=r"(r[28]), "=r"(r[29]), "=r"(r[30]), "=r"(r[31])
        : "r"(addr));
}
__device__ __forceinline__ void mma_f16_ss(uint32_t d, uint64_t a_desc,
                                           uint64_t b_desc, uint32_t idesc,
                                           uint32_t en) {
    asm volatile(
        "{\n\t.reg .pred p;\n\t"
        "setp.ne.u32 p, %5, 0;\n\t"
        "tcgen05.mma.cta_group::1.kind::f16 [%0], %1, %2, %3, {%4, %4, %4, %4}, p;\n\t}"
        :: "r"(d), "l"(a_desc), "l"(b_desc), "r"(idesc), "r"(0u), "r"(en)
        : "memory");
}
__device__ __forceinline__ uint64_t make_desc(uint32_t addr) {
    return ((uint64_t)2 << 61) | ((uint64_t)1 << 46) | ((uint64_t)64 << 32) |
           ((uint64_t)1 << 16) | (((uint64_t)(addr >> 4)) & 0x3FFF);
}
__device__ __forceinline__ void fma2(float2 &c, const float2 &a, const float2 &b) {
    unsigned long long       &cc = reinterpret_cast<unsigned long long &>(c);
    const unsigned long long &aa = reinterpret_cast<const unsigned long long &>(a);
    const unsigned long long &bb = reinterpret_cast<const unsigned long long &>(b);
    asm("fma.rn.f32x2 %0, %1, %2, %0;" : "+l"(cc) : "l"(aa), "l"(bb));
}
__device__ __forceinline__ void split1(float v, __nv_bfloat16 &h, __nv_bfloat16 &l) {
    h = __float2bfloat16(v);
    l = __float2bfloat16(v - __bfloat162float(h));
}
__device__ __forceinline__ uint32_t pack2(__nv_bfloat16 a, __nv_bfloat16 b) {
    __nv_bfloat162 p(a, b);
    return *reinterpret_cast<uint32_t *>(&p);
}

static constexpr uint32_t TC_IDESC = 0x8200490u; // F32 acc, BF16xBF16, M=128, N=128

__device__ __forceinline__ uint32_t sw16(int r, int ch) {  // 128x64 bf16 tile (16KB)
    uint32_t byte = (r >> 3) * 1024 + (r & 7) * 128 + ch * 16;
    return byte ^ ((byte >> 3) & 0x70);
}
__device__ __forceinline__ uint32_t sw32(int r, int ch) {  // 128x128 bf16 tile (32KB)
    uint32_t byte = ((r >> 3) + (ch >> 3) * 16) * 1024 + (r & 7) * 128 + (ch & 7) * 16;
    return byte ^ ((byte >> 3) & 0x70);
}

// ---------------------------------------------------------------------------
// tc_skinny_f32: C[128-mtile, 128] += alpha * split(A_f32)[M,K] @ (Bhi+Blo)[128,K]^T
// A is fp32, hi/lo-split in-kernel (registers -> swizzled smem).
// split-K over gridDim.z (kpc per z, multiple of 64); Kvalid predicates A loads.
// red.v4 epilogue (caller zero-fills C).
// smem: 1KB hdr + 2 stages x (Ahi 16K + Alo 16K + Bhi 16K + Blo 16K)
// ---------------------------------------------------------------------------
#define SKF_SMEM (1024 + 2 * 65536)

__global__ void __launch_bounds__(128)
tc_skinny_f32(const float *__restrict__ A, int lda, int Kvalid,
              const __nv_bfloat16 *__restrict__ Bhi,
              const __nv_bfloat16 *__restrict__ Blo, int ldb,
              float *__restrict__ C, int ldc, int kpc, float alpha)
{
#if TC_ENABLED
    extern __shared__ char sm[];
    const uint32_t sb = cvta_smem(sm);
    const int tid = threadIdx.x;
    const int wid = tid >> 5;

    if (wid == 0) tc_alloc(sb, 128);
    if (tid == 64) mbar_init(sb + 8, 1);
    __syncthreads();
    uint32_t tmem;
    asm volatile("ld.shared.b32 %0, [%1];" : "=r"(tmem) : "r"(sb));

    const int m0 = blockIdx.x * 128;
    const int kb0 = blockIdx.z * kpc;
    const int S = kpc >> 6;

    float4 regs[16];

    auto ldA = [&](int s) {
        const int kb = kb0 + s * 64;
#pragma unroll
        for (int i = 0; i < 16; ++i) {
            int g = i * 128 + tid;
            int r = g >> 4, ch = g & 15;
            int col = kb + ch * 4;
            if (col < Kvalid)
                regs[i] = *(const float4 *)(A + (size_t)(m0 + r) * lda + col);
            else
                regs[i] = make_float4(0.f, 0.f, 0.f, 0.f);
        }
    };
    auto ldB = [&](int s) {
        const uint32_t bh = sb + 1024 + (s & 1) * 65536 + 32768;
        const int kb = kb0 + s * 64;
#pragma unroll
        for (int i = 0; i < 8; ++i) {
            int g = i * 128 + tid;
            int r = g >> 3, ch = g & 7;
            uint32_t so = sw16(r, ch);
            cpa16(bh + so,         Bhi + (size_t)r * ldb + kb + ch * 8);
            cpa16(bh + 16384 + so, Blo + (size_t)r * ldb + kb + ch * 8);
        }
        cpa_commit();
    };
    auto stA = [&](int s) {
        char *ah = sm + 1024 + (s & 1) * 65536;
        char *al = ah + 16384;
#pragma unroll
        for (int i = 0; i < 16; ++i) {
            int g = i * 128 + tid;
            int r = g >> 4, ch = g & 15;
            float4 v = regs[i];
            __nv_bfloat16 h0, h1, h2, h3, l0, l1, l2, l3;
            split1(v.x, h0, l0); split1(v.y, h1, l1);
            split1(v.z, h2, l2); split1(v.w, h3, l3);
            uint32_t b = (uint32_t)(r * 128 + ch * 8);
            uint32_t sz = b ^ ((b >> 3) & 0x70);
            *(uint2 *)(ah + sz) = make_uint2(pack2(h0, h1), pack2(h2, h3));
            *(uint2 *)(al + sz) = make_uint2(pack2(l0, l1), pack2(l2, l3));
        }
    };

    ldB(0);
    ldA(0);
    uint32_t ph = 0;
    for (int s = 0; s < S; ++s) {
        cpa_wait<0>();     // B(s) in smem
        stA(s);            // regs(s) -> swizzled hi/lo smem
        __syncthreads();
        fence_async_smem();
        if (wid == 0 && elect_one()) {
            const uint32_t base = sb + 1024 + (s & 1) * 65536;
            uint64_t dah = make_desc(base);
            uint64_t dal = make_desc(base + 16384);
            uint64_t dbh = make_desc(base + 32768);
            uint64_t dbl = make_desc(base + 49152);
#pragma unroll
            for (int k = 0; k < 4; ++k) {
                uint64_t off = (uint64_t)(k * 2);
                mma_f16_ss(tmem, dah + off, dbh + off, TC_IDESC, (s > 0) || (k > 0));
                mma_f16_ss(tmem, dah + off, dbl + off, TC_IDESC, 1u);
                mma_f16_ss(tmem, dal + off, dbh + off, TC_IDESC, 1u);
            }
            tc_commit(sb + 8);
        }
        if (s + 1 < S) { ldB(s + 1); ldA(s + 1); }  // overlap MMA
        mbar_wait(sb + 8, ph);
        ph ^= 1;
        __syncthreads();
    }

    tc_fence_after();
#pragma unroll
    for (int part = 0; part < 4; ++part) {
        uint32_t d[32];
        ldtm32(d, tmem + part * 32);
        tc_wait_ld();
        float *cp = C + (size_t)(m0 + tid) * ldc + part * 32;
#pragma unroll
        for (int j = 0; j < 8; ++j)
            red4(cp + j * 4,
                 __uint_as_float(d[j * 4 + 0]) * alpha,
                 __uint_as_float(d[j * 4 + 1]) * alpha,
                 __uint_as_float(d[j * 4 + 2]) * alpha,
                 __uint_as_float(d[j * 4 + 3]) * alpha);
    }
    __syncthreads();
    if (wid == 0) {
        tc_relinquish();
        tc_dealloc(tmem, 128);
    }
#endif
}

// ---------------------------------------------------------------------------
// tc_wide: logits. C[128-mtile, 512-ngroup] = alpha*(Ahi+Alo)@(Bhi+Blo)^T, K=128
// ---------------------------------------------------------------------------
#define WIDE_SMEM (1024 + 65536 + 131072)

__global__ void __launch_bounds__(128)
tc_wide(const __nv_bfloat16 *__restrict__ Ahi, const __nv_bfloat16 *__restrict__ Alo,
        const __nv_bfloat16 *__restrict__ Bhi, const __nv_bfloat16 *__restrict__ Blo,
        float *__restrict__ C, float alpha)
{
#if TC_ENABLED
    extern __shared__ char sm[];
    const uint32_t sb = cvta_smem(sm);
    const int tid = threadIdx.x;
    const int wid = tid >> 5;

    if (wid == 0) tc_alloc(sb, 512);
    if (tid == 64) mbar_init(sb + 8, 1);
    __syncthreads();
    uint32_t tmem;
    asm volatile("ld.shared.b32 %0, [%1];" : "=r"(tmem) : "r"(sb));

    const int m0 = blockIdx.x * 128;
    const int ng0 = blockIdx.y * 512;

    const uint32_t A0 = sb + 1024;
    const uint32_t A1 = A0 + 32768;

    auto load_B = [&](int n) {
        const uint32_t base = sb + 1024 + 65536 + (n & 1) * 65536;
        const int r0 = ng0 + n * 128;
#pragma unroll
        for (int i = tid; i < 2048; i += 128) {
            int r = i >> 4, ch = i & 15;
            uint32_t so = sw32(r, ch);
            cpa16(base + so,         Bhi + (size_t)(r0 + r) * HDIM + ch * 8);
            cpa16(base + 32768 + so, Blo + (size_t)(r0 + r) * HDIM + ch * 8);
        }
        cpa_commit();
    };

#pragma unroll
    for (int i = tid; i < 2048; i += 128) {
        int r = i >> 4, ch = i & 15;
        uint32_t so = sw32(r, ch);
        cpa16(A0 + so, Ahi + (size_t)(m0 + r) * HDIM + ch * 8);
        cpa16(A1 + so, Alo + (size_t)(m0 + r) * HDIM + ch * 8);
    }
    {
        const uint32_t base = sb + 1024 + 65536;
#pragma unroll
        for (int i = tid; i < 2048; i += 128) {
            int r = i >> 4, ch = i & 15;
            uint32_t so = sw32(r, ch);
            cpa16(base + so,         Bhi + (size_t)(ng0 + r) * HDIM + ch * 8);
            cpa16(base + 32768 + so, Blo + (size_t)(ng0 + r) * HDIM + ch * 8);
        }
    }
    cpa_commit();

    uint32_t ph = 0;
    for (int n = 0; n < 4; ++n) {
        if (n + 1 < 4) { load_B(n + 1); cpa_wait<1>(); }
        else           { cpa_wait<0>(); }
        __syncthreads();
        fence_async_smem();
        if (wid == 0 && elect_one()) {
            const uint32_t bbase = sb + 1024 + 65536 + (n & 1) * 65536;
            uint64_t dah = make_desc(A0);
            uint64_t dal = make_desc(A1);
            uint64_t dbh = make_desc(bbase);
            uint64_t dbl = make_desc(bbase + 32768);
            const uint32_t acc = tmem + n * 128;
#pragma unroll
            for (int k = 0; k < 8; ++k) {
                uint64_t off = (uint64_t)((k & 3) * 2 + (k >> 2) * 1024);
                mma_f16_ss(acc, dah + off, dbh + off, TC_IDESC, k > 0);
                mma_f16_ss(acc, dah + off, dbl + off, TC_IDESC, 1u);
                mma_f16_ss(acc, dal + off, dbh + off, TC_IDESC, 1u);
            }
            tc_commit(sb + 8);
        }
        mbar_wait(sb + 8, ph);
        ph ^= 1;
        __syncthreads();
    }

    tc_fence_after();
    float *st = (float *)(sm + 1024);
    for (int n = 0; n < 4; ++n) {
#pragma unroll
        for (int part = 0; part < 4; ++part) {
            uint32_t d[32];
            ldtm32(d, tmem + n * 128 + part * 32);
            tc_wait_ld();
#pragma unroll
            for (int c = 0; c < 32; ++c)
                st[tid * 33 + c] = __uint_as_float(d[c]) * alpha;
            __syncthreads();
            const int col0 = ng0 + n * 128 + part * 32;
#pragma unroll
            for (int i = 0; i < 32; ++i) {
                int idx = i * 128 + tid;
                int rr = idx >> 5, cc = idx & 31;
                C[(size_t)(m0 + rr) * NCELL + col0 + cc] = st[rr * 33 + cc];
            }
            __syncthreads();
        }
    }
    __syncthreads();
    if (wid == 0) {
        tc_relinquish();
        tc_dealloc(tmem, 512);
    }
#endif
}

// ---------------------------------------------------------------------------
// fp32 -> bf16 hi/lo split kernels (small operands only)
// ---------------------------------------------------------------------------
__global__ void split_cols(const float *__restrict__ src, int ldsrc, int col0,
                           int cols4, __nv_bfloat16 *__restrict__ hi,
                           __nv_bfloat16 *__restrict__ lo)
{
    int idx = blockIdx.x * blockDim.x + threadIdx.x;
    int r = idx / cols4, c = idx - r * cols4;
    float4 v = *(const float4 *)(src + (size_t)r * ldsrc + col0 + c * 4);
    __nv_bfloat16 h0, h1, h2, h3, l0, l1, l2, l3;
    split1(v.x, h0, l0); split1(v.y, h1, l1);
    split1(v.z, h2, l2); split1(v.w, h3, l3);
    __nv_bfloat162 *ph = (__nv_bfloat162 *)(hi + (size_t)idx * 4);
    __nv_bfloat162 *pl = (__nv_bfloat162 *)(lo + (size_t)idx * 4);
    ph[0] = __nv_bfloat162(h0, h1); ph[1] = __nv_bfloat162(h2, h3);
    pl[0] = __nv_bfloat162(l0, l1); pl[1] = __nv_bfloat162(l2, l3);
}

// enc_W[hid] [2000,128] -> wT hi/lo [128,2048] (transposed, zero-padded)
__global__ void wT_split(const float *__restrict__ W, const int *__restrict__ hid,
                         __nv_bfloat16 *__restrict__ hi, __nv_bfloat16 *__restrict__ lo)
{
    int idx = blockIdx.x * blockDim.x + threadIdx.x;   // 128*2048
    int r = idx >> 7;        // k index 0..2047
    int c = idx & 127;       // output col 0..127
    const float *Wh = W + (size_t)hid[0] * NINP * HDIM;
    float v = (r < NINP) ? Wh[(size_t)r * HDIM + c] : 0.f;
    __nv_bfloat16 h, l;
    split1(v, h, l);
    size_t o = (size_t)c * KPAD + r;
    hi[o] = h;
    lo[o] = l;
}

// transpose + split: dst[c, r] = src[r, col0 + c], dst is [128, NCELL]
__global__ void transpose_split(const float *__restrict__ src, int ldsrc, int col0,
                                __nv_bfloat16 *__restrict__ hi,
                                __nv_bfloat16 *__restrict__ lo)
{
    __shared__ float t[32][33];
    int r0 = blockIdx.x * 32, c0 = blockIdx.y * 32;
    int tx = threadIdx.x, ty = threadIdx.y;  // 32 x 8
#pragma unroll
    for (int i = 0; i < 4; ++i) {
        int r = ty + i * 8;
        t[r][tx] = src[(size_t)(r0 + r) * ldsrc + col0 + c0 + tx];
    }
    __syncthreads();
#pragma unroll
    for (int i = 0; i < 4; ++i) {
        int c = ty + i * 8;
        float v = t[tx][c];
        __nv_bfloat16 h, l;
        split1(v, h, l);
        size_t o = (size_t)(c0 + c) * NCELL + r0 + tx;
        hi[o] = h;
        lo[o] = l;
    }
}

// ---------------------------------------------------------------------------
// fp32 tiled SGEMM (small GEMMs): C = alpha*A@B (+bias), split-K red.v4
// ---------------------------------------------------------------------------
template <bool NT, bool ATOMIC>
__global__ void __launch_bounds__(256)
gemm_tile(const float *__restrict__ A, const float *__restrict__ Bbase,
          float *__restrict__ C,
          int lda, int ldb, int ldc, int K,
          float alpha, const float *__restrict__ bias,
          const int *__restrict__ hid, long long headStride)
{
    const float *B = Bbase + (hid ? (long long)hid[0] * headStride : 0);

    __shared__ float As[BK][BM + 4];
    __shared__ float Bs[BK][BN + 4];

    const int tid = threadIdx.x;
    const int tx = tid & 15;
    const int ty = tid >> 4;
    const int m0 = blockIdx.x * BM;
    const int n0 = blockIdx.y * BN;

    const int chunks = K / BK;
    const int nz = gridDim.z, z = blockIdx.z;
    const int per = chunks / nz, rem = chunks % nz;
    const int c0 = z * per + (z < rem ? z : rem);
    const int c1 = c0 + per + (z < rem ? 1 : 0);

    const int f0 = tid, f1 = tid + 256;
    const int aRow0 = f0 >> 2, aK0 = (f0 & 3) * 4;
    const int aRow1 = f1 >> 2, aK1 = (f1 & 3) * 4;
    const int bK0 = f0 >> 5, bN0 = (f0 & 31) * 4;
    const int bK1 = f1 >> 5, bN1 = (f1 & 31) * 4;

    const float *Ap0 = A + (size_t)(m0 + aRow0) * lda + (size_t)c0 * BK + aK0;
    const float *Ap1 = A + (size_t)(m0 + aRow1) * lda + (size_t)c0 * BK + aK1;
    const float *Bp0, *Bp1;
    if (NT) {
        Bp0 = B + (size_t)(n0 + aRow0) * ldb + (size_t)c0 * BK + aK0;
        Bp1 = B + (size_t)(n0 + aRow1) * ldb + (size_t)c0 * BK + aK1;
    } else {
        Bp0 = B + (size_t)(c0 * BK + bK0) * ldb + n0 + bN0;
        Bp1 = B + (size_t)(c0 * BK + bK1) * ldb + n0 + bN1;
    }

    float2 acc[8][4];
#pragma unroll
    for (int i = 0; i < 8; ++i)
#pragma unroll
        for (int j = 0; j < 4; ++j) acc[i][j] = make_float2(0.f, 0.f);

    float4 ra0 = *(const float4 *)Ap0;
    float4 ra1 = *(const float4 *)Ap1;
    float4 rb0 = *(const float4 *)Bp0;
    float4 rb1 = *(const float4 *)Bp1;

    for (int c = c0; c < c1; ++c) {
        __syncthreads();
        As[aK0 + 0][aRow0] = ra0.x; As[aK0 + 1][aRow0] = ra0.y;
        As[aK0 + 2][aRow0] = ra0.z; As[aK0 + 3][aRow0] = ra0.w;
        As[aK1 + 0][aRow1] = ra1.x; As[aK1 + 1][aRow1] = ra1.y;
        As[aK1 + 2][aRow1] = ra1.z; As[aK1 + 3][aRow1] = ra1.w;
        if (NT) {
            Bs[aK0 + 0][aRow0] = rb0.x; Bs[aK0 + 1][aRow0] = rb0.y;
            Bs[aK0 + 2][aRow0] = rb0.z; Bs[aK0 + 3][aRow0] = rb0.w;
            Bs[aK1 + 0][aRow1] = rb1.x; Bs[aK1 + 1][aRow1] = rb1.y;
            Bs[aK1 + 2][aRow1] = rb1.z; Bs[aK1 + 3][aRow1] = rb1.w;
        } else {
            *(float4 *)&Bs[bK0][bN0] = rb0;
            *(float4 *)&Bs[bK1][bN1] = rb1;
        }
        __syncthreads();

        if (c + 1 < c1) {
            Ap0 += BK; Ap1 += BK;
            ra0 = *(const float4 *)Ap0;
            ra1 = *(const float4 *)Ap1;
            if (NT) {
                Bp0 += BK; Bp1 += BK;
            } else {
                Bp0 += (size_t)BK * ldb; Bp1 += (size_t)BK * ldb;
            }
            rb0 = *(const float4 *)Bp0;
            rb1 = *(const float4 *)Bp1;
        }

#pragma unroll
        for (int kk = 0; kk < BK; ++kk) {
            float4 a0 = *(const float4 *)&As[kk][ty * 4];
            float4 a1 = *(const float4 *)&As[kk][64 + ty * 4];
            float4 b0 = *(const float4 *)&Bs[kk][tx * 4];
            float4 b1 = *(const float4 *)&Bs[kk][64 + tx * 4];
            float av[8] = {a0.x, a0.y, a0.z, a0.w, a1.x, a1.y, a1.z, a1.w};
            float2 bp[4] = {make_float2(b0.x, b0.y), make_float2(b0.z, b0.w),
                            make_float2(b1.x, b1.y), make_float2(b1.z, b1.w)};
#pragma unroll
            for (int i = 0; i < 8; ++i) {
                float2 aa = make_float2(av[i], av[i]);
#pragma unroll
                for (int j = 0; j < 4; ++j) fma2(acc[i][j], aa, bp[j]);
            }
        }
    }

    float bad0[4] = {0.f, 0.f, 0.f, 0.f}, bad1[4] = {0.f, 0.f, 0.f, 0.f};
    if (bias != nullptr && blockIdx.z == 0) {
#pragma unroll
        for (int j = 0; j < 4; ++j) {
            bad0[j] = bias[n0 + tx * 4 + j];
            bad1[j] = bias[n0 + 64 + tx * 4 + j];
        }
    }
#pragma unroll
    for (int i = 0; i < 8; ++i) {
        int r = m0 + ((i < 4) ? (ty * 4 + i) : (64 + ty * 4 + (i - 4)));
        float v[8] = {acc[i][0].x, acc[i][0].y, acc[i][1].x, acc[i][1].y,
                      acc[i][2].x, acc[i][2].y, acc[i][3].x, acc[i][3].y};
        float *crow = C + (size_t)r * ldc;
        if (ATOMIC) {
            red4(crow + n0 + tx * 4,
                 v[0] * alpha + bad0[0], v[1] * alpha + bad0[1],
                 v[2] * alpha + bad0[2], v[3] * alpha + bad0[3]);
            red4(crow + n0 + 64 + tx * 4,
                 v[4] * alpha + bad1[0], v[5] * alpha + bad1[1],
                 v[6] * alpha + bad1[2], v[7] * alpha + bad1[3]);
        } else {
            float4 w0 = make_float4(v[0] * alpha + bad0[0], v[1] * alpha + bad0[1],
                                    v[2] * alpha + bad0[2], v[3] * alpha + bad0[3]);
            float4 w1 = make_float4(v[4] * alpha + bad1[0], v[5] * alpha + bad1[1],
                                    v[6] * alpha + bad1[2], v[7] * alpha + bad1[3]);
            *(float4 *)(crow + n0 + tx * 4) = w0;
            *(float4 *)(crow + n0 + 64 + tx * 4) = w1;
        }
    }
}

// ---------------------------------------------------------------------------
// BatchNorm (training-mode) + ReLU
// ---------------------------------------------------------------------------
__global__ void bn_stats(const float *__restrict__ h, float *__restrict__ stats)
{
    int col = threadIdx.x;
    int r0 = blockIdx.x * 32;          // 256 blocks x 32 rows
    float s = 0.f, s2 = 0.f;
#pragma unroll 8
    for (int r = 0; r < 32; ++r) {
        float v = h[(size_t)(r0 + r) * HDIM + col];
        s += v; s2 += v * v;
    }
    atomicAdd(&stats[col], s);
    atomicAdd(&stats[128 + col], s2);
}

__global__ void bn_finalize(float *__restrict__ stats,
                            const float *__restrict__ g, const float *__restrict__ be,
                            const int *__restrict__ hid, int headStride)
{
    int c = threadIdx.x;
    int off = hid ? hid[0] * headStride : 0;
    float mean = stats[c] * (1.f / (float)NCELL);
    float var = stats[128 + c] * (1.f / (float)NCELL) - mean * mean;
    float rstd = rsqrtf(var + BN_EPS);
    float gg = g[off + c];
    stats[256 + c] = gg * rstd;
    stats[384 + c] = be[off + c] - gg * mean * rstd;
}

__global__ void bn_apply(float *__restrict__ h, const float *__restrict__ stats)
{
    const float *scale = stats + 256;
    const float *shift = stats + 384;
    int i = blockIdx.x * blockDim.x + threadIdx.x;
    float4 v = ((float4 *)h)[i];
    int c = (i * 4) & (HDIM - 1);
    v.x = fmaxf(v.x * scale[c + 0] + shift[c + 0], 0.f);
    v.y = fmaxf(v.y * scale[c + 1] + shift[c + 1], 0.f);
    v.z = fmaxf(v.z * scale[c + 2] + shift[c + 2], 0.f);
    v.w = fmaxf(v.w * scale[c + 3] + shift[c + 3], 0.f);
    ((float4 *)h)[i] = v;
}

// ---------------------------------------------------------------------------
// Row softmax, in-place fp32 (T3 reads the fp32 result directly)
// ---------------------------------------------------------------------------
__global__ void softmax_row(float *__restrict__ attn)
{
    extern __shared__ float row[];
    __shared__ float red[256];
    const int t = threadIdx.x;
    float *p = attn + (size_t)blockIdx.x * NCELL;

    float m = -1e30f;
    for (int i = t; i < NCELL / 4; i += 256) {
        float4 v = ((const float4 *)p)[i];
        ((float4 *)row)[i] = v;
        m = fmaxf(m, fmaxf(fmaxf(v.x, v.y), fmaxf(v.z, v.w)));
    }
    red[t] = m; __syncthreads();
    for (int s = 128; s > 0; s >>= 1) {
        if (t < s) red[t] = fmaxf(red[t], red[t + s]);
        __syncthreads();
    }
    const float bmax = red[0];
    __syncthreads();

    float sum = 0.f;
    for (int i = t; i < NCELL / 4; i += 256) {
        float4 v = ((float4 *)row)[i];
        v.x = __expf(v.x - bmax); v.y = __expf(v.y - bmax);
        v.z = __expf(v.z - bmax); v.w = __expf(v.w - bmax);
        sum += v.x + v.y + v.z + v.w;
        ((float4 *)row)[i] = v;
    }
    red[t] = sum; __syncthreads();
    for (int s = 128; s > 0; s >>= 1) {
        if (t < s) red[t] += red[t + s];
        __syncthreads();
    }
    const float inv = 1.f / red[0];
    __syncthreads();

    for (int i = t; i < NCELL / 4; i += 256) {
        float4 v = ((float4 *)row)[i];
        v.x *= inv; v.y *= inv; v.z *= inv; v.w *= inv;
        ((float4 *)p)[i] = v;
    }
}

// ---------------------------------------------------------------------------
// Variational heads
// ---------------------------------------------------------------------------
__global__ void heads_kernel(const float *__restrict__ o,
                             const float *__restrict__ mW, const float *__restrict__ mb,
                             const float *__restrict__ vW, const float *__restrict__ vb,
                             const float *__restrict__ eps,
                             float *__restrict__ qm, float *__restrict__ qv,
                             float *__restrict__ lat)
{
    extern __shared__ float smh[];
    float *Wm  = smh;
    float *Wv  = smh + 4096;
    float *osm = smh + 8192;
    const int t = threadIdx.x;
    const int r0 = blockIdx.x * 128;

    for (int i = t; i < HDIM * NOUTD; i += 256) { Wm[i] = mW[i]; Wv[i] = vW[i]; }
    for (int i = t; i < 128 * HDIM; i += 256) {
        int r = i >> 7, c = i & 127;
        osm[r * 129 + c] = o[(size_t)(r0 + r) * HDIM + c];
    }
    __syncthreads();

    for (int idx = t; idx < 128 * NOUTD; idx += 256) {
        int r = idx >> 5, c = idx & 31;
        const float *orow = &osm[r * 129];
        float dm = 0.f, dv = 0.f;
#pragma unroll 8
        for (int k = 0; k < HDIM; ++k) {
            float ov = orow[k];
            dm += ov * Wm[k * NOUTD + c];
            dv += ov * Wv[k * NOUTD + c];
        }
        int R = r0 + r;
        float mval = dm + mb[c];
        float vval = __expf(dv + vb[c]);
        qm[R * NOUTD + c]  = mval;
        qv[R * NOUTD + c]  = vval;
        lat[R * NOUTD + c] = mval + sqrtf(vval) * eps[R * NOUTD + c];
    }
}

// ---------------------------------------------------------------------------
// Launch
// ---------------------------------------------------------------------------
extern "C" void kernel_launch(void *const *d_in, const int *in_sizes, int n_in,
                              void *d_out, int out_size)
{
    const float *x       = (const float *)d_in[0];
    const float *spatial = (const float *)d_in[1];
    const float *eps     = (const float *)d_in[2];
    const float *enc_W   = (const float *)d_in[3];
    const float *enc_g   = (const float *)d_in[5];
    const float *enc_be  = (const float *)d_in[6];
    const float *sh_W1   = (const float *)d_in[7];
    const float *sh_g1   = (const float *)d_in[9];
    const float *sh_be1  = (const float *)d_in[10];
    const float *sh_W2   = (const float *)d_in[11];
    const float *sh_g2   = (const float *)d_in[13];
    const float *sh_be2  = (const float *)d_in[14];
    const float *qkv_W   = (const float *)d_in[15];
    const float *qkv_b   = (const float *)d_in[16];
    const float *o_W     = (const float *)d_in[17];
    const float *o_b     = (const float *)d_in[18];
    const float *mean_W  = (const float *)d_in[19];
    const float *mean_b  = (const float *)d_in[20];
    const float *var_W   = (const float *)d_in[21];
    const float *var_b   = (const float *)d_in[22];
    const int   *hid     = (const int *)d_in[23];

    float *out = (float *)d_out;
    float *out_qm   = out;
    float *out_qv   = out + (size_t)NCELL * NOUTD;
    float *out_lat  = out + 2 * (size_t)NCELL * NOUTD;
    float *out_attn = out + 3 * (size_t)NCELL * NOUTD;

    float *bufA, *bufB, *qkv, *kagg, *stats;
    __nv_bfloat16 *q_hi, *q_lo, *ka_hi, *ka_lo;
    __nv_bfloat16 *kT_hi, *kT_lo, *vT_hi, *vT_lo, *wT_hi, *wT_lo;
    cudaGetSymbolAddress((void **)&bufA, g_bufA);
    cudaGetSymbolAddress((void **)&bufB, g_bufB);
    cudaGetSymbolAddress((void **)&qkv,  g_qkv);
    cudaGetSymbolAddress((void **)&kagg, g_kagg);
    cudaGetSymbolAddress((void **)&stats, g_stats);
    cudaGetSymbolAddress((void **)&q_hi, g_q_hi);
    cudaGetSymbolAddress((void **)&q_lo, g_q_lo);
    cudaGetSymbolAddress((void **)&ka_hi, g_ka_hi);
    cudaGetSymbolAddress((void **)&ka_lo, g_ka_lo);
    cudaGetSymbolAddress((void **)&kT_hi, g_kT_hi);
    cudaGetSymbolAddress((void **)&kT_lo, g_kT_lo);
    cudaGetSymbolAddress((void **)&vT_hi, g_vT_hi);
    cudaGetSymbolAddress((void **)&vT_lo, g_vT_lo);
    cudaGetSymbolAddress((void **)&wT_hi, g_wT_hi);
    cudaGetSymbolAddress((void **)&wT_lo, g_wT_lo);

    cudaFuncSetAttribute(tc_skinny_f32, cudaFuncAttributeMaxDynamicSharedMemorySize, SKF_SMEM);
    cudaFuncSetAttribute(tc_wide,       cudaFuncAttributeMaxDynamicSharedMemorySize, WIDE_SMEM);

    const size_t NH_BYTES = (size_t)NCELL * HDIM * sizeof(float);
    const float SCALE = 0.08838834764831845f; // 1/sqrt(128)

    // 1. encoder: h = x @ enc_W[hid]  (fp32 A split in-kernel; bias cancels in BN)
    wT_split<<<1024, 256>>>(enc_W, hid, wT_hi, wT_lo);
    cudaMemsetAsync(bufA, 0, NH_BYTES);
    tc_skinny_f32<<<dim3(64, 1, 8), 128, SKF_SMEM>>>(
        x, NINP, NINP, wT_hi, wT_lo, KPAD, bufA, HDIM, 256, 1.f);
    cudaMemsetAsync(stats, 0, 256 * sizeof(float));
    bn_stats<<<256, 128>>>(bufA, stats);
    bn_finalize<<<1, 128>>>(stats, enc_g, enc_be, hid, HDIM);
    bn_apply<<<1024, 256>>>(bufA, stats);

    // 2. shared layer 1
    cudaMemsetAsync(bufB, 0, NH_BYTES);
    gemm_tile<false, true><<<dim3(64, 1, 2), 256>>>(
        bufA, sh_W1, bufB, HDIM, HDIM, HDIM, HDIM, 1.f, nullptr, nullptr, 0);
    cudaMemsetAsync(stats, 0, 256 * sizeof(float));
    bn_stats<<<256, 128>>>(bufB, stats);
    bn_finalize<<<1, 128>>>(stats, sh_g1, sh_be1, nullptr, 0);
    bn_apply<<<1024, 256>>>(bufB, stats);

    // 3. shared layer 2
    cudaMemsetAsync(bufA, 0, NH_BYTES);
    gemm_tile<false, true><<<dim3(64, 1, 2), 256>>>(
        bufB, sh_W2, bufA, HDIM, HDIM, HDIM, HDIM, 1.f, nullptr, nullptr, 0);
    cudaMemsetAsync(stats, 0, 256 * sizeof(float));
    bn_stats<<<256, 128>>>(bufA, stats);
    bn_finalize<<<1, 128>>>(stats, sh_g2, sh_be2, nullptr, 0);
    bn_apply<<<1024, 256>>>(bufA, stats);

    // 4. qkv projection
    cudaMemsetAsync(qkv, 0, (size_t)NCELL * 3 * HDIM * sizeof(float));
    gemm_tile<false, true><<<dim3(64, 3, 2), 256>>>(
        bufA, qkv_W, qkv, HDIM, 3 * HDIM, 3 * HDIM, HDIM, 1.f, qkv_b, nullptr, 0);

    // 5. small bf16 conversions (q, kT, vT)
    split_cols<<<1024, 256>>>(qkv, 3 * HDIM, 0, HDIM / 4, q_hi, q_lo);
    transpose_split<<<dim3(256, 4), dim3(32, 8)>>>(qkv, 3 * HDIM, HDIM, kT_hi, kT_lo);
    transpose_split<<<dim3(256, 4), dim3(32, 8)>>>(qkv, 3 * HDIM, 2 * HDIM, vT_hi, vT_lo);

    // 6. k_agg = spatial @ k   (spatial fp32 split in-kernel)
    cudaMemsetAsync(kagg, 0, NH_BYTES);
    tc_skinny_f32<<<dim3(64, 1, 8), 128, SKF_SMEM>>>(
        spatial, NCELL, NCELL, kT_hi, kT_lo, NCELL, kagg, HDIM, 1024, 1.f);
    split_cols<<<1024, 256>>>(kagg, HDIM, 0, HDIM / 4, ka_hi, ka_lo);

    // 7. logits = (q @ k_agg^T) / sqrt(H)  -> out_attn
    tc_wide<<<dim3(64, 16), 128, WIDE_SMEM>>>(q_hi, q_lo, ka_hi, ka_lo, out_attn, SCALE);

    // 8. softmax in place (fp32 only)
    softmax_row<<<NCELL, 256, NCELL * sizeof(float)>>>(out_attn);

    // 9. av = attn @ v    (attn fp32 read + split in-kernel)
    cudaMemsetAsync(bufA, 0, NH_BYTES);
    tc_skinny_f32<<<dim3(64, 1, 8), 128, SKF_SMEM>>>(
        out_attn, NCELL, NCELL, vT_hi, vT_lo, NCELL, bufA, HDIM, 1024, 1.f);

    // 10. o = av @ o_W + o_b
    cudaMemsetAsync(bufB, 0, NH_BYTES);
    gemm_tile<false, true><<<dim3(64, 1, 2), 256>>>(
        bufA, o_W, bufB, HDIM, HDIM, HDIM, HDIM, 1.f, o_b, nullptr, 0);

    // 11. variational heads
    const int heads_smem = (4096 + 4096 + 128 * 129) * sizeof(float);
    cudaFuncSetAttribute(heads_kernel, cudaFuncAttributeMaxDynamicSharedMemorySize,
                         heads_smem);
    heads_kernel<<<64, 256, heads_smem>>>(bufB, mean_W, mean_b, var_W, var_b,
                                          eps, out_qm, out_qv, out_lat);
}